// round 11
// baseline (speedup 1.0000x reference)
#include <cuda_runtime.h>
#include <cuda_bf16.h>
#include <cstdint>

// ---------------- problem constants ----------------
#define BATCH   32
#define CIN     256
#define NPIX    4096
#define HID     128
#define HEADS   4
#define DH      32
#define QSCALE  0.17677669529663687f
#define GN_EPS  1e-5f
#define NEL_F   1048576.0f

// ---------------- scratch (device globals; no runtime alloc) -------------
__device__ __nv_bfloat16 g_xth[(size_t)BATCH * NPIX * CIN];
__device__ __nv_bfloat16 g_xtl[(size_t)BATCH * NPIX * CIN];
__device__ __nv_bfloat16 g_wqh[384 * CIN];
__device__ __nv_bfloat16 g_wql[384 * CIN];
__device__ __nv_bfloat16 g_qh[(size_t)BATCH * NPIX * HID];
__device__ __nv_bfloat16 g_ql[(size_t)BATCH * NPIX * HID];
__device__ float g_k[(size_t)BATCH * HID * NPIX];
__device__ float g_v[(size_t)BATCH * HID * NPIX];
__device__ float g_ctx[BATCH * HEADS * DH * DH];
__device__ __nv_bfloat16 g_wph[BATCH * 256 * HID];
__device__ __nv_bfloat16 g_wpl[BATCH * 256 * HID];
__device__ float g_stats[BATCH * 2];

// ---------------- helpers ----------------
__device__ __forceinline__ uint32_t s2u(const void* p) {
    uint32_t a;
    asm("{ .reg .u64 t; cvta.to.shared.u64 t, %1; cvt.u32.u64 %0, t; }" : "=r"(a) : "l"(p));
    return a;
}
__device__ __forceinline__ uint32_t pack_bf(__nv_bfloat16 a, __nv_bfloat16 b) {
    return (uint32_t)__bfloat16_as_ushort(a) | ((uint32_t)__bfloat16_as_ushort(b) << 16);
}
__device__ __forceinline__ void split_bf(float x, __nv_bfloat16& h, __nv_bfloat16& l) {
    h = __float2bfloat16(x);
    l = __float2bfloat16(x - __bfloat162float(h));
}

__device__ __forceinline__ void mma_bf16(float d[4],
    uint32_t a0, uint32_t a1, uint32_t a2, uint32_t a3,
    uint32_t b0, uint32_t b1)
{
    asm("mma.sync.aligned.m16n8k16.row.col.f32.bf16.bf16.f32 "
        "{%0,%1,%2,%3}, {%4,%5,%6,%7}, {%8,%9}, {%0,%1,%2,%3};"
        : "+f"(d[0]), "+f"(d[1]), "+f"(d[2]), "+f"(d[3])
        : "r"(a0), "r"(a1), "r"(a2), "r"(a3), "r"(b0), "r"(b1));
}
__device__ __forceinline__ void ldsm4(uint32_t r[4], uint32_t addr) {
    asm volatile("ldmatrix.sync.aligned.m8n8.x4.shared.b16 {%0,%1,%2,%3}, [%4];"
        : "=r"(r[0]), "=r"(r[1]), "=r"(r[2]), "=r"(r[3]) : "r"(addr));
}
#define CPA(dst, src) asm volatile("cp.async.cg.shared.global [%0], [%1], 16;" :: "r"(dst), "l"(src))
#define CPC()  asm volatile("cp.async.commit_group;" ::: "memory")
#define CPW0() asm volatile("cp.async.wait_group 0;" ::: "memory")
#define CPW1() asm volatile("cp.async.wait_group 1;" ::: "memory")

// ---------------- GEMM core (identical to R7) ----------------------------
#define ARR_B  (128 * 64)
#define STAGE1 (4 * ARR_B)
#define SROW 129
#define S_BYTES (128 * SROW * 4)
#define BIAS_OFF (3 * STAGE1)
#define SMEM_BYTES (BIAS_OFF + 512)

__device__ __forceinline__ uint32_t swadr(uint32_t sb, int arr, int row, int seg) {
    return sb + arr * ARR_B + row * 64 + (((uint32_t)(seg ^ ((row >> 1) & 3))) << 4);
}

__device__ __forceinline__ void stage_issue(
    uint32_t sb,
    const __nv_bfloat16* __restrict__ Ah, const __nv_bfloat16* __restrict__ Al, int lda,
    const __nv_bfloat16* __restrict__ Bh, const __nv_bfloat16* __restrict__ Bl, int ldb,
    int kc)
{
    const int tid = threadIdx.x;
    const __nv_bfloat16* gs[4] = {Ah, Al, Bh, Bl};
    #pragma unroll
    for (int j = 0; j < 8; j++) {
        const int arr = j >> 1;
        const int ld  = (arr < 2) ? lda : ldb;
        const int idx = tid + (j & 1) * 256;
        const int r   = idx >> 2;
        const int s   = idx & 3;
        const __nv_bfloat16* src = gs[arr] + (size_t)r * ld + kc + s * 8;
        CPA(swadr(sb, arr, r, s), src);
    }
    CPC();
}

__device__ __forceinline__ void chunk_compute(uint32_t sb, float acc[4][4][4]) {
    const int lane = threadIdx.x & 31;
    const int wid  = threadIdx.x >> 5;
    const int wm   = (wid >> 2) * 64;
    const int wn   = (wid & 3) * 32;
    const int ra   = lane & 15;
    const int sa   = lane >> 4;
    const int rb   = ((lane >> 4) & 1) * 8 + (lane & 7);
    const int sbg  = (lane >> 3) & 1;

    uint32_t aad[4][2], bad[2][2];
    #pragma unroll
    for (int mt = 0; mt < 4; mt++) {
        int row = wm + mt * 16 + ra;
        aad[mt][0] = swadr(sb, 0, row, sa);
        aad[mt][1] = swadr(sb, 1, row, sa);
    }
    #pragma unroll
    for (int pr = 0; pr < 2; pr++) {
        int row = wn + pr * 16 + rb;
        bad[pr][0] = swadr(sb, 2, row, sbg);
        bad[pr][1] = swadr(sb, 3, row, sbg);
    }

    #pragma unroll
    for (int ks = 0; ks < 2; ks++) {
        const uint32_t xr = ks ? 0x20u : 0u;
        uint32_t ah[4][4], al[4][4], bh[2][4], bl[2][4];
        #pragma unroll
        for (int mt = 0; mt < 4; mt++) {
            ldsm4(ah[mt], aad[mt][0] ^ xr);
            ldsm4(al[mt], aad[mt][1] ^ xr);
        }
        #pragma unroll
        for (int pr = 0; pr < 2; pr++) {
            ldsm4(bh[pr], bad[pr][0] ^ xr);
            ldsm4(bl[pr], bad[pr][1] ^ xr);
        }
        #pragma unroll
        for (int mt = 0; mt < 4; mt++)
            #pragma unroll
            for (int nt = 0; nt < 4; nt++) {
                uint32_t b0h = bh[nt >> 1][(nt & 1) * 2], b1h = bh[nt >> 1][(nt & 1) * 2 + 1];
                uint32_t b0l = bl[nt >> 1][(nt & 1) * 2], b1l = bl[nt >> 1][(nt & 1) * 2 + 1];
                mma_bf16(acc[mt][nt], ah[mt][0], ah[mt][1], ah[mt][2], ah[mt][3], b0h, b1h);
                mma_bf16(acc[mt][nt], ah[mt][0], ah[mt][1], ah[mt][2], ah[mt][3], b0l, b1l);
                mma_bf16(acc[mt][nt], al[mt][0], al[mt][1], al[mt][2], al[mt][3], b0h, b1h);
            }
    }
}

template<int KTOT>
__device__ __forceinline__ void gemm_block(
    const __nv_bfloat16* __restrict__ Ah, const __nv_bfloat16* __restrict__ Al, int lda,
    const __nv_bfloat16* __restrict__ Bh, const __nv_bfloat16* __restrict__ Bl, int ldb,
    uint32_t sbase, float acc[4][4][4])
{
    constexpr int NCHUNK = KTOT / 32;
    stage_issue(sbase, Ah, Al, lda, Bh, Bl, ldb, 0);
    if (NCHUNK > 1) stage_issue(sbase + STAGE1, Ah, Al, lda, Bh, Bl, ldb, 32);
    #pragma unroll 1
    for (int c = 0; c < NCHUNK; c++) {
        if (c + 1 < NCHUNK) { CPW1(); } else { CPW0(); }
        __syncthreads();
        if (c + 2 < NCHUNK) {
            const uint32_t nbuf = sbase + ((c + 2) % 3) * STAGE1;
            stage_issue(nbuf, Ah, Al, lda, Bh, Bl, ldb, (c + 2) * 32);
        }
        chunk_compute(sbase + (c % 3) * STAGE1, acc);
    }
    __syncthreads();
}

__device__ __forceinline__ void acc_to_smem(float* S, float acc[4][4][4]) {
    const int lane = threadIdx.x & 31;
    const int wid  = threadIdx.x >> 5;
    const int wm   = (wid >> 2) * 64;
    const int wn   = (wid & 3) * 32;
    #pragma unroll
    for (int mt = 0; mt < 4; mt++)
        #pragma unroll
        for (int nt = 0; nt < 4; nt++) {
            int r = wm + mt * 16 + (lane >> 2);
            int c = wn + nt * 8 + (lane & 3) * 2;
            S[r * SROW + c]           = acc[mt][nt][0];
            S[r * SROW + c + 1]       = acc[mt][nt][1];
            S[(r + 8) * SROW + c]     = acc[mt][nt][2];
            S[(r + 8) * SROW + c + 1] = acc[mt][nt][3];
        }
    __syncthreads();
}

// ---------------- kernel: transpose + bf16 split of x --------------------
__global__ void __launch_bounds__(128) k_conv(const float* __restrict__ x) {
    __shared__ float s[32][129];
    const int tid = threadIdx.x;
    const int n0 = blockIdx.x * 128;
    const int c0 = blockIdx.y * 32;
    const int b  = blockIdx.z;

    #pragma unroll
    for (int cc = 0; cc < 32; cc++)
        s[cc][tid] = x[((size_t)b * CIN + c0 + cc) * NPIX + n0 + tid];
    __syncthreads();

    uint32_t pkh[16], pkl[16];
    #pragma unroll
    for (int cc = 0; cc < 32; cc += 2) {
        __nv_bfloat16 h0, l0, h1, l1;
        split_bf(s[cc][tid], h0, l0);
        split_bf(s[cc + 1][tid], h1, l1);
        pkh[cc >> 1] = pack_bf(h0, h1);
        pkl[cc >> 1] = pack_bf(l0, l1);
    }
    const size_t eb = ((size_t)b * NPIX + n0 + tid) * CIN + c0;
    uint4* dh = (uint4*)&g_xth[eb];
    uint4* dl = (uint4*)&g_xtl[eb];
    #pragma unroll
    for (int q = 0; q < 4; q++) {
        dh[q] = make_uint4(pkh[q*4], pkh[q*4+1], pkh[q*4+2], pkh[q*4+3]);
        dl[q] = make_uint4(pkl[q*4], pkl[q*4+1], pkl[q*4+2], pkl[q*4+3]);
    }
}

// ---------------- kernel: bf16 split of Wqkv + zero accumulators ---------
__global__ void k_wconv(const float* __restrict__ W) {
    int i = blockIdx.x * 256 + threadIdx.x;
    if (i < 384 * CIN) {
        __nv_bfloat16 h, l;
        split_bf(W[i], h, l);
        g_wqh[i] = h; g_wql[i] = l;
    }
    if (i < BATCH * HEADS * DH * DH) g_ctx[i] = 0.f;
    if (i < BATCH * 2) g_stats[i] = 0.f;
}

// ---------------- kernel: QKV GEMM + softmax epilogue --------------------
__global__ void __launch_bounds__(256, 2) k_qkv_mma(const float* __restrict__ bqkv)
{
    extern __shared__ char smem[];
    const uint32_t sbase = s2u(smem);
    float* S = (float*)smem;
    float* bias_s = (float*)(smem + BIAS_OFF);
    const int tid = threadIdx.x;
    const int n0 = blockIdx.x * 128;
    const int m  = blockIdx.y;
    const int b  = blockIdx.z;

    if (tid < 128) bias_s[tid] = bqkv[m * 128 + tid];

    float acc[4][4][4];
    #pragma unroll
    for (int i = 0; i < 4; i++)
        #pragma unroll
        for (int j = 0; j < 4; j++)
            #pragma unroll
            for (int q = 0; q < 4; q++) acc[i][j][q] = 0.f;

    gemm_block<CIN>(g_wqh + m * 128 * CIN, g_wql + m * 128 * CIN, CIN,
                    g_xth + ((size_t)b * NPIX + n0) * CIN,
                    g_xtl + ((size_t)b * NPIX + n0) * CIN, CIN,
                    sbase, acc);
    acc_to_smem(S, acc);

    const int col = tid & 127;
    const int half = tid >> 7;
    const int pixel = n0 + col;

    if (m == 2) {
        #pragma unroll 4
        for (int r = half * 64; r < half * 64 + 64; r++)
            g_v[((size_t)b * HID + r) * NPIX + pixel] = S[r * SROW + col] + bias_s[r];
        return;
    }
    #pragma unroll
    for (int g = 0; g < 2; g++) {
        const int rb = half * 64 + g * 32;
        float v[32];
        float mx = -1e30f;
        #pragma unroll
        for (int j = 0; j < 32; j++) {
            v[j] = S[(rb + j) * SROW + col] + bias_s[rb + j];
            mx = fmaxf(mx, v[j]);
        }
        float s = 0.f;
        #pragma unroll
        for (int j = 0; j < 32; j++) { v[j] = __expf(v[j] - mx); s += v[j]; }
        float inv = 1.f / s;
        if (m == 0) inv *= QSCALE;
        if (m == 1) {
            #pragma unroll
            for (int j = 0; j < 32; j++)
                g_k[((size_t)b * HID + rb + j) * NPIX + pixel] = v[j] * inv;
        } else {
            uint32_t pkh[16], pkl[16];
            #pragma unroll
            for (int j = 0; j < 32; j += 2) {
                __nv_bfloat16 h0, l0, h1, l1;
                split_bf(v[j] * inv, h0, l0);
                split_bf(v[j + 1] * inv, h1, l1);
                pkh[j >> 1] = pack_bf(h0, h1);
                pkl[j >> 1] = pack_bf(l0, l1);
            }
            size_t e = ((size_t)b * NPIX + pixel) * HID + rb;
            uint4* dh = (uint4*)&g_qh[e];
            uint4* dl = (uint4*)&g_ql[e];
            #pragma unroll
            for (int q = 0; q < 4; q++) {
                dh[q] = make_uint4(pkh[q*4], pkh[q*4+1], pkh[q*4+2], pkh[q*4+3]);
                dl[q] = make_uint4(pkl[q*4], pkl[q*4+1], pkl[q*4+2], pkl[q*4+3]);
            }
        }
    }
}

// ---------------- kernel: context[b,h,d,e] = sum_n k'[d,n] v[e,n] --------
// 32 threads (1 warp), 8x4 register tile per thread:
// per nn: 3 LDS.128 (48 B) for 32 FFMA -> 1.5 B/FMA (was 2 B/FMA).
// grid (128 bh, 16 segments of 256 n)
#define CROW 36
__global__ void __launch_bounds__(32) k_ctx()
{
    __shared__ float Ks[64][CROW];
    __shared__ float Vs[64][CROW];

    const int bh = blockIdx.x;
    const int seg = blockIdx.y;
    const int b = bh >> 2, h = bh & 3;
    const int tid = threadIdx.x;
    const int d0 = (tid >> 3) * 8;     // {0,8,16,24}
    const int e0 = (tid & 7) * 4;      // {0,4,...,28}

    float acc[8][4];
    #pragma unroll
    for (int i = 0; i < 8; i++)
        #pragma unroll
        for (int j = 0; j < 4; j++) acc[i][j] = 0.f;

    const float* kp = g_k + ((size_t)b * HID + h * DH) * NPIX + seg * 256;
    const float* vp = g_v + ((size_t)b * HID + h * DH) * NPIX + seg * 256;

    #pragma unroll 1
    for (int c0 = 0; c0 < 256; c0 += 64) {
        __syncwarp();
        // thread stages pixel columns tid and tid+32 (rows of Ks/Vs)
        #pragma unroll
        for (int r = 0; r < 2; r++) {
            const int row = tid + r * 32;
            #pragma unroll
            for (int d = 0; d < 32; d++) {
                Ks[row][d] = kp[(size_t)d * NPIX + c0 + row];
                Vs[row][d] = vp[(size_t)d * NPIX + c0 + row];
            }
        }
        __syncwarp();
        #pragma unroll 4
        for (int nn = 0; nn < 64; nn++) {
            float4 k0 = *(const float4*)&Ks[nn][d0];
            float4 k1 = *(const float4*)&Ks[nn][d0 + 4];
            float4 vv = *(const float4*)&Vs[nn][e0];
            float ka[8] = {k0.x, k0.y, k0.z, k0.w, k1.x, k1.y, k1.z, k1.w};
            float va[4] = {vv.x, vv.y, vv.z, vv.w};
            #pragma unroll
            for (int i = 0; i < 8; i++)
                #pragma unroll
                for (int j = 0; j < 4; j++)
                    acc[i][j] += ka[i] * va[j];
        }
    }
    float* cdst = g_ctx + ((b * HEADS + h) * DH + d0) * DH + e0;
    #pragma unroll
    for (int i = 0; i < 8; i++)
        #pragma unroll
        for (int j = 0; j < 4; j++)
            atomicAdd(cdst + i * DH + j, acc[i][j]);
}

// ---------------- kernel: fold Wout with context -> bf16 hi/lo -----------
// ctx staged with 33-padded rows (scalar access only): bank (hd+e)%32.
__global__ void __launch_bounds__(256) k_wp(const float* __restrict__ Wout)
{
    __shared__ float ctxs[HEADS * DH * 33];
    const int b = blockIdx.x;
    const int obase = blockIdx.y * 32;

    for (int i = threadIdx.x; i < HEADS * DH * DH; i += 256)
        ctxs[(i >> 5) * 33 + (i & 31)] = g_ctx[b * HEADS * DH * DH + i];
    __syncthreads();

    int hd = threadIdx.x & 127;
    int hb = hd & 0xE0;
    for (int oi = threadIdx.x >> 7; oi < 32; oi += 2) {
        int o = obase + oi;
        float s = 0.f;
        #pragma unroll
        for (int e = 0; e < 32; e++)
            s += Wout[o * HID + hb + e] * ctxs[hd * 33 + e];
        __nv_bfloat16 h, l;
        split_bf(s, h, l);
        size_t idx = ((size_t)b * 256 + o) * HID + hd;
        g_wph[idx] = h;
        g_wpl[idx] = l;
    }
}

// ---------------- kernel: projection GEMM + GN stats ---------------------
__global__ void __launch_bounds__(256, 2) k_proj_mma(
    const float* __restrict__ bout, float* __restrict__ out)
{
    extern __shared__ char smem[];
    const uint32_t sbase = s2u(smem);
    float* S = (float*)smem;
    float* bias_s = (float*)(smem + BIAS_OFF);
    const int tid = threadIdx.x;
    const int n0 = blockIdx.x * 128;
    const int o0 = blockIdx.y * 128;
    const int b  = blockIdx.z;

    if (tid < 128) bias_s[tid] = bout[o0 + tid];

    float acc[4][4][4];
    #pragma unroll
    for (int i = 0; i < 4; i++)
        #pragma unroll
        for (int j = 0; j < 4; j++)
            #pragma unroll
            for (int q = 0; q < 4; q++) acc[i][j][q] = 0.f;

    gemm_block<HID>(g_wph + ((size_t)b * 256 + o0) * HID,
                    g_wpl + ((size_t)b * 256 + o0) * HID, HID,
                    g_qh + ((size_t)b * NPIX + n0) * HID,
                    g_ql + ((size_t)b * NPIX + n0) * HID, HID,
                    sbase, acc);
    acc_to_smem(S, acc);

    const int col = tid & 127;
    const int half = tid >> 7;
    const int pixel = n0 + col;
    float lsum = 0.f, lsq = 0.f;

    #pragma unroll 4
    for (int r = half * 64; r < half * 64 + 64; r++) {
        float val = S[r * SROW + col] + bias_s[r];
        lsum += val;
        lsq  += val * val;
        out[((size_t)b * 256 + o0 + r) * NPIX + pixel] = val;
    }
    #pragma unroll
    for (int off = 16; off > 0; off >>= 1) {
        lsum += __shfl_down_sync(0xffffffffu, lsum, off);
        lsq  += __shfl_down_sync(0xffffffffu, lsq,  off);
    }
    if ((tid & 31) == 0) {
        atomicAdd(&g_stats[b * 2 + 0], lsum);
        atomicAdd(&g_stats[b * 2 + 1], lsq);
    }
}

// ---------------- kernel: groupnorm normalize (in place) -----------------
__global__ void __launch_bounds__(256) k_norm(
    const float* __restrict__ gamma, const float* __restrict__ beta,
    float* __restrict__ out)
{
    size_t idx = ((size_t)blockIdx.x * 256 + threadIdx.x) * 4;
    int b = (int)(idx >> 20);
    int c = (int)((idx >> 12) & 255);
    float s1 = g_stats[b * 2 + 0];
    float s2 = g_stats[b * 2 + 1];
    float mu  = s1 * (1.f / NEL_F);
    float var = s2 * (1.f / NEL_F) - mu * mu;
    float rs = rsqrtf(var + GN_EPS);
    float gm = gamma[c] * rs;
    float bb = beta[c] - mu * gm;
    float4 v = *(const float4*)&out[idx];
    v.x = v.x * gm + bb;
    v.y = v.y * gm + bb;
    v.z = v.z * gm + bb;
    v.w = v.w * gm + bb;
    *(float4*)&out[idx] = v;
}

// ---------------- launch ----------------
extern "C" void kernel_launch(void* const* d_in, const int* in_sizes, int n_in,
                              void* d_out, int out_size)
{
    const float* x     = (const float*)d_in[0];
    const float* Wqkv  = (const float*)d_in[1];
    const float* bqkv  = (const float*)d_in[2];
    const float* Wout  = (const float*)d_in[3];
    const float* bout  = (const float*)d_in[4];
    const float* gamma = (const float*)d_in[5];
    const float* beta  = (const float*)d_in[6];
    float* out = (float*)d_out;

    static bool attr_done = false;
    if (!attr_done) {
        cudaFuncSetAttribute(k_qkv_mma,  cudaFuncAttributeMaxDynamicSharedMemorySize, SMEM_BYTES);
        cudaFuncSetAttribute(k_proj_mma, cudaFuncAttributeMaxDynamicSharedMemorySize, SMEM_BYTES);
        attr_done = true;
    }

    k_conv <<<dim3(32, 8, 32), 128>>>(x);
    k_wconv<<<512, 256>>>(Wqkv);
    k_qkv_mma <<<dim3(32, 3, 32), 256, SMEM_BYTES>>>(bqkv);
    k_ctx  <<<dim3(128, 16), 32>>>();
    k_wp   <<<dim3(32, 8), 256>>>(Wout);
    k_proj_mma<<<dim3(32, 2, 32), 256, SMEM_BYTES>>>(bout, out);
    k_norm <<<32768, 256>>>(gamma, beta, out);
}

// round 12
// speedup vs baseline: 1.1786x; 1.1786x over previous
#include <cuda_runtime.h>
#include <cuda_fp16.h>
#include <cstdint>

// ---------------- problem constants ----------------
#define BATCH   32
#define CIN     256
#define NPIX    4096
#define HID     128
#define HEADS   4
#define DH      32
#define QSCALE  0.17677669529663687f
#define GN_EPS  1e-5f
#define NEL_F   1048576.0f

// ---------------- scratch (device globals; no runtime alloc) -------------
__device__ __half g_xth[(size_t)BATCH * NPIX * CIN];   // x^T hi [b][n][c]
__device__ __half g_xtl[(size_t)BATCH * NPIX * CIN];   // x^T lo
__device__ __half g_wqh[384 * CIN];                    // Wqkv fp16 [o][c]
__device__ __half g_qh[(size_t)BATCH * NPIX * HID];    // q' hi [b][n][c]
__device__ __half g_ql[(size_t)BATCH * NPIX * HID];    // q' lo
__device__ float g_k[(size_t)BATCH * HID * NPIX];
__device__ float g_v[(size_t)BATCH * HID * NPIX];
__device__ float g_ctx[BATCH * HEADS * DH * DH];
__device__ __half g_wph[BATCH * 256 * HID];            // W' fp16 [b][o][c]
__device__ float g_stats[BATCH * 2];

// ---------------- helpers ----------------
__device__ __forceinline__ uint32_t s2u(const void* p) {
    uint32_t a;
    asm("{ .reg .u64 t; cvta.to.shared.u64 t, %1; cvt.u32.u64 %0, t; }" : "=r"(a) : "l"(p));
    return a;
}
__device__ __forceinline__ uint32_t pack_h(__half a, __half b) {
    return (uint32_t)__half_as_ushort(a) | ((uint32_t)__half_as_ushort(b) << 16);
}
__device__ __forceinline__ void split_h(float x, __half& h, __half& l) {
    h = __float2half(x);
    l = __float2half(x - __half2float(h));
}

__device__ __forceinline__ void mma_f16(float d[4],
    uint32_t a0, uint32_t a1, uint32_t a2, uint32_t a3,
    uint32_t b0, uint32_t b1)
{
    asm("mma.sync.aligned.m16n8k16.row.col.f32.f16.f16.f32 "
        "{%0,%1,%2,%3}, {%4,%5,%6,%7}, {%8,%9}, {%0,%1,%2,%3};"
        : "+f"(d[0]), "+f"(d[1]), "+f"(d[2]), "+f"(d[3])
        : "r"(a0), "r"(a1), "r"(a2), "r"(a3), "r"(b0), "r"(b1));
}
__device__ __forceinline__ void ldsm4(uint32_t r[4], uint32_t addr) {
    asm volatile("ldmatrix.sync.aligned.m8n8.x4.shared.b16 {%0,%1,%2,%3}, [%4];"
        : "=r"(r[0]), "=r"(r[1]), "=r"(r[2]), "=r"(r[3]) : "r"(addr));
}
#define CPA(dst, src) asm volatile("cp.async.cg.shared.global [%0], [%1], 16;" :: "r"(dst), "l"(src))
#define CPC()  asm volatile("cp.async.commit_group;" ::: "memory")
#define CPW0() asm volatile("cp.async.wait_group 0;" ::: "memory")
#define CPW1() asm volatile("cp.async.wait_group 1;" ::: "memory")

// ---------------- GEMM core: fp16 2-term --------------------------------
// Block tile M=128 x N=128; D = A(fp16) . (Bh + Bl)^T, fp32 accum.
// 3 staged arrays per chunk: A, Bh, Bl (64B swizzled rows, 32-K chunks).
// 3 buffers, 2 cp.async groups in flight, one sync per chunk.
#define ARR_B  (128 * 64)                   // 8192 bytes per array
#define STAGE1 (3 * ARR_B)                  // 24576 per stage
#define SROW 129
#define S_BYTES (128 * SROW * 4)            // 66048 (aliases stage area)
#define BIAS_OFF (3 * STAGE1)               // 73728
#define SMEM_BYTES (BIAS_OFF + 512)         // 74240

__device__ __forceinline__ uint32_t swadr(uint32_t sb, int arr, int row, int seg) {
    return sb + arr * ARR_B + row * 64 + (((uint32_t)(seg ^ ((row >> 1) & 3))) << 4);
}

__device__ __forceinline__ void stage_issue(
    uint32_t sb,
    const __half* __restrict__ A, int lda,
    const __half* __restrict__ Bh, const __half* __restrict__ Bl, int ldb,
    int kc)
{
    const int tid = threadIdx.x;
    const __half* gs[3] = {A, Bh, Bl};
    #pragma unroll
    for (int j = 0; j < 6; j++) {
        const int arr = j >> 1;
        const int ld  = (arr == 0) ? lda : ldb;
        const int idx = tid + (j & 1) * 256;     // 0..511
        const int r   = idx >> 2;
        const int s   = idx & 3;
        const __half* src = gs[arr] + (size_t)r * ld + kc + s * 8;
        CPA(swadr(sb, arr, r, s), src);
    }
    CPC();
}

__device__ __forceinline__ void chunk_compute(uint32_t sb, float acc[4][4][4]) {
    const int lane = threadIdx.x & 31;
    const int wid  = threadIdx.x >> 5;
    const int wm   = (wid >> 2) * 64;
    const int wn   = (wid & 3) * 32;
    const int ra   = lane & 15;
    const int sa   = lane >> 4;
    const int rb   = ((lane >> 4) & 1) * 8 + (lane & 7);
    const int sbg  = (lane >> 3) & 1;

    uint32_t aad[4], bad[2][2];
    #pragma unroll
    for (int mt = 0; mt < 4; mt++)
        aad[mt] = swadr(sb, 0, wm + mt * 16 + ra, sa);
    #pragma unroll
    for (int pr = 0; pr < 2; pr++) {
        int row = wn + pr * 16 + rb;
        bad[pr][0] = swadr(sb, 1, row, sbg);
        bad[pr][1] = swadr(sb, 2, row, sbg);
    }

    #pragma unroll
    for (int ks = 0; ks < 2; ks++) {
        const uint32_t xr = ks ? 0x20u : 0u;
        uint32_t ah[4][4], bh[2][4], bl[2][4];
        #pragma unroll
        for (int mt = 0; mt < 4; mt++)
            ldsm4(ah[mt], aad[mt] ^ xr);
        #pragma unroll
        for (int pr = 0; pr < 2; pr++) {
            ldsm4(bh[pr], bad[pr][0] ^ xr);
            ldsm4(bl[pr], bad[pr][1] ^ xr);
        }
        #pragma unroll
        for (int mt = 0; mt < 4; mt++)
            #pragma unroll
            for (int nt = 0; nt < 4; nt++) {
                uint32_t b0h = bh[nt >> 1][(nt & 1) * 2], b1h = bh[nt >> 1][(nt & 1) * 2 + 1];
                uint32_t b0l = bl[nt >> 1][(nt & 1) * 2], b1l = bl[nt >> 1][(nt & 1) * 2 + 1];
                mma_f16(acc[mt][nt], ah[mt][0], ah[mt][1], ah[mt][2], ah[mt][3], b0h, b1h);
                mma_f16(acc[mt][nt], ah[mt][0], ah[mt][1], ah[mt][2], ah[mt][3], b0l, b1l);
            }
    }
}

template<int KTOT>
__device__ __forceinline__ void gemm_block(
    const __half* __restrict__ A, int lda,
    const __half* __restrict__ Bh, const __half* __restrict__ Bl, int ldb,
    uint32_t sbase, float acc[4][4][4])
{
    constexpr int NCHUNK = KTOT / 32;
    stage_issue(sbase, A, lda, Bh, Bl, ldb, 0);
    if (NCHUNK > 1) stage_issue(sbase + STAGE1, A, lda, Bh, Bl, ldb, 32);
    #pragma unroll 1
    for (int c = 0; c < NCHUNK; c++) {
        if (c + 1 < NCHUNK) { CPW1(); } else { CPW0(); }
        __syncthreads();
        if (c + 2 < NCHUNK) {
            const uint32_t nbuf = sbase + ((c + 2) % 3) * STAGE1;
            stage_issue(nbuf, A, lda, Bh, Bl, ldb, (c + 2) * 32);
        }
        chunk_compute(sbase + (c % 3) * STAGE1, acc);
    }
    __syncthreads();
}

__device__ __forceinline__ void acc_to_smem(float* S, float acc[4][4][4]) {
    const int lane = threadIdx.x & 31;
    const int wid  = threadIdx.x >> 5;
    const int wm   = (wid >> 2) * 64;
    const int wn   = (wid & 3) * 32;
    #pragma unroll
    for (int mt = 0; mt < 4; mt++)
        #pragma unroll
        for (int nt = 0; nt < 4; nt++) {
            int r = wm + mt * 16 + (lane >> 2);
            int c = wn + nt * 8 + (lane & 3) * 2;
            S[r * SROW + c]           = acc[mt][nt][0];
            S[r * SROW + c + 1]       = acc[mt][nt][1];
            S[(r + 8) * SROW + c]     = acc[mt][nt][2];
            S[(r + 8) * SROW + c + 1] = acc[mt][nt][3];
        }
    __syncthreads();
}

// ---------------- kernel: transpose + fp16 split of x --------------------
__global__ void __launch_bounds__(128) k_conv(const float* __restrict__ x) {
    __shared__ float s[32][129];
    const int tid = threadIdx.x;
    const int n0 = blockIdx.x * 128;
    const int c0 = blockIdx.y * 32;
    const int b  = blockIdx.z;

    #pragma unroll
    for (int cc = 0; cc < 32; cc++)
        s[cc][tid] = x[((size_t)b * CIN + c0 + cc) * NPIX + n0 + tid];
    __syncthreads();

    uint32_t pkh[16], pkl[16];
    #pragma unroll
    for (int cc = 0; cc < 32; cc += 2) {
        __half h0, l0, h1, l1;
        split_h(s[cc][tid], h0, l0);
        split_h(s[cc + 1][tid], h1, l1);
        pkh[cc >> 1] = pack_h(h0, h1);
        pkl[cc >> 1] = pack_h(l0, l1);
    }
    const size_t eb = ((size_t)b * NPIX + n0 + tid) * CIN + c0;
    uint4* dh = (uint4*)&g_xth[eb];
    uint4* dl = (uint4*)&g_xtl[eb];
    #pragma unroll
    for (int q = 0; q < 4; q++) {
        dh[q] = make_uint4(pkh[q*4], pkh[q*4+1], pkh[q*4+2], pkh[q*4+3]);
        dl[q] = make_uint4(pkl[q*4], pkl[q*4+1], pkl[q*4+2], pkl[q*4+3]);
    }
}

// ---------------- kernel: fp16 convert Wqkv + zero accumulators ----------
__global__ void k_wconv(const float* __restrict__ W) {
    int i = blockIdx.x * 256 + threadIdx.x;
    if (i < 384 * CIN) g_wqh[i] = __float2half(W[i]);
    if (i < BATCH * HEADS * DH * DH) g_ctx[i] = 0.f;
    if (i < BATCH * 2) g_stats[i] = 0.f;
}

// ---------------- kernel: QKV GEMM + softmax epilogue --------------------
__global__ void __launch_bounds__(256, 2) k_qkv_mma(const float* __restrict__ bqkv)
{
    extern __shared__ char smem[];
    const uint32_t sbase = s2u(smem);
    float* S = (float*)smem;
    float* bias_s = (float*)(smem + BIAS_OFF);
    const int tid = threadIdx.x;
    const int n0 = blockIdx.x * 128;
    const int m  = blockIdx.y;
    const int b  = blockIdx.z;

    if (tid < 128) bias_s[tid] = bqkv[m * 128 + tid];

    float acc[4][4][4];
    #pragma unroll
    for (int i = 0; i < 4; i++)
        #pragma unroll
        for (int j = 0; j < 4; j++)
            #pragma unroll
            for (int q = 0; q < 4; q++) acc[i][j][q] = 0.f;

    gemm_block<CIN>(g_wqh + m * 128 * CIN, CIN,
                    g_xth + ((size_t)b * NPIX + n0) * CIN,
                    g_xtl + ((size_t)b * NPIX + n0) * CIN, CIN,
                    sbase, acc);
    acc_to_smem(S, acc);

    const int col = tid & 127;
    const int half = tid >> 7;
    const int pixel = n0 + col;

    if (m == 2) {
        #pragma unroll 4
        for (int r = half * 64; r < half * 64 + 64; r++)
            g_v[((size_t)b * HID + r) * NPIX + pixel] = S[r * SROW + col] + bias_s[r];
        return;
    }
    #pragma unroll
    for (int g = 0; g < 2; g++) {
        const int rb = half * 64 + g * 32;
        float v[32];
        float mx = -1e30f;
        #pragma unroll
        for (int j = 0; j < 32; j++) {
            v[j] = S[(rb + j) * SROW + col] + bias_s[rb + j];
            mx = fmaxf(mx, v[j]);
        }
        float s = 0.f;
        #pragma unroll
        for (int j = 0; j < 32; j++) { v[j] = __expf(v[j] - mx); s += v[j]; }
        float inv = 1.f / s;
        if (m == 0) inv *= QSCALE;
        if (m == 1) {
            #pragma unroll
            for (int j = 0; j < 32; j++)
                g_k[((size_t)b * HID + rb + j) * NPIX + pixel] = v[j] * inv;
        } else {
            uint32_t pkh[16], pkl[16];
            #pragma unroll
            for (int j = 0; j < 32; j += 2) {
                __half h0, l0, h1, l1;
                split_h(v[j] * inv, h0, l0);
                split_h(v[j + 1] * inv, h1, l1);
                pkh[j >> 1] = pack_h(h0, h1);
                pkl[j >> 1] = pack_h(l0, l1);
            }
            size_t e = ((size_t)b * NPIX + pixel) * HID + rb;
            uint4* dh = (uint4*)&g_qh[e];
            uint4* dl = (uint4*)&g_ql[e];
            #pragma unroll
            for (int q = 0; q < 4; q++) {
                dh[q] = make_uint4(pkh[q*4], pkh[q*4+1], pkh[q*4+2], pkh[q*4+3]);
                dl[q] = make_uint4(pkl[q*4], pkl[q*4+1], pkl[q*4+2], pkl[q*4+3]);
            }
        }
    }
}

// ---------------- kernel: context[b,h,d,e] = sum_n k'[d,n] v[e,n] --------
// (R7 version, best measured: 64 threads, 4x4 tile)
__global__ void __launch_bounds__(64) k_ctx()
{
    __shared__ float Ks[32][65];
    __shared__ float Vs[32][65];

    const int bh = blockIdx.x;
    const int seg = blockIdx.y;
    const int b = bh >> 2, h = bh & 3;
    const int tid = threadIdx.x;
    const int d0 = (tid >> 3) * 4;
    const int e0 = (tid & 7) * 4;

    float acc[4][4];
    #pragma unroll
    for (int i = 0; i < 4; i++)
        #pragma unroll
        for (int j = 0; j < 4; j++) acc[i][j] = 0.f;

    const float* kp = g_k + ((size_t)b * HID + h * DH) * NPIX + seg * 256;
    const float* vp = g_v + ((size_t)b * HID + h * DH) * NPIX + seg * 256;

    #pragma unroll 1
    for (int c0 = 0; c0 < 256; c0 += 64) {
        __syncthreads();
        #pragma unroll
        for (int i = 0; i < 32; i++) {
            Ks[i][tid] = kp[(size_t)i * NPIX + c0 + tid];
            Vs[i][tid] = vp[(size_t)i * NPIX + c0 + tid];
        }
        __syncthreads();
        #pragma unroll 4
        for (int nn = 0; nn < 64; nn++) {
            float ka[4], va[4];
            #pragma unroll
            for (int i = 0; i < 4; i++) ka[i] = Ks[d0 + i][nn];
            #pragma unroll
            for (int j = 0; j < 4; j++) va[j] = Vs[e0 + j][nn];
            #pragma unroll
            for (int i = 0; i < 4; i++)
                #pragma unroll
                for (int j = 0; j < 4; j++)
                    acc[i][j] += ka[i] * va[j];
        }
    }
    float* cdst = g_ctx + ((b * HEADS + h) * DH + d0) * DH + e0;
    #pragma unroll
    for (int i = 0; i < 4; i++)
        #pragma unroll
        for (int j = 0; j < 4; j++)
            atomicAdd(cdst + i * DH + j, acc[i][j]);
}

// ---------------- kernel: fold Wout with context -> fp16 -----------------
__global__ void __launch_bounds__(256) k_wp(const float* __restrict__ Wout)
{
    __shared__ float ctxs[HEADS * DH * 33];
    const int b = blockIdx.x;
    const int obase = blockIdx.y * 32;

    for (int i = threadIdx.x; i < HEADS * DH * DH; i += 256)
        ctxs[(i >> 5) * 33 + (i & 31)] = g_ctx[b * HEADS * DH * DH + i];
    __syncthreads();

    int hd = threadIdx.x & 127;
    int hb = hd & 0xE0;
    for (int oi = threadIdx.x >> 7; oi < 32; oi += 2) {
        int o = obase + oi;
        float s = 0.f;
        #pragma unroll
        for (int e = 0; e < 32; e++)
            s += Wout[o * HID + hb + e] * ctxs[hd * 33 + e];
        g_wph[((size_t)b * 256 + o) * HID + hd] = __float2half(s);
    }
}

// ---------------- kernel: projection GEMM + GN stats ---------------------
__global__ void __launch_bounds__(256, 2) k_proj_mma(
    const float* __restrict__ bout, float* __restrict__ out)
{
    extern __shared__ char smem[];
    const uint32_t sbase = s2u(smem);
    float* S = (float*)smem;
    float* bias_s = (float*)(smem + BIAS_OFF);
    const int tid = threadIdx.x;
    const int n0 = blockIdx.x * 128;
    const int o0 = blockIdx.y * 128;
    const int b  = blockIdx.z;

    if (tid < 128) bias_s[tid] = bout[o0 + tid];

    float acc[4][4][4];
    #pragma unroll
    for (int i = 0; i < 4; i++)
        #pragma unroll
        for (int j = 0; j < 4; j++)
            #pragma unroll
            for (int q = 0; q < 4; q++) acc[i][j][q] = 0.f;

    gemm_block<HID>(g_wph + ((size_t)b * 256 + o0) * HID, HID,
                    g_qh + ((size_t)b * NPIX + n0) * HID,
                    g_ql + ((size_t)b * NPIX + n0) * HID, HID,
                    sbase, acc);
    acc_to_smem(S, acc);

    const int col = tid & 127;
    const int half = tid >> 7;
    const int pixel = n0 + col;
    float lsum = 0.f, lsq = 0.f;

    #pragma unroll 4
    for (int r = half * 64; r < half * 64 + 64; r++) {
        float val = S[r * SROW + col] + bias_s[r];
        lsum += val;
        lsq  += val * val;
        out[((size_t)b * 256 + o0 + r) * NPIX + pixel] = val;
    }
    #pragma unroll
    for (int off = 16; off > 0; off >>= 1) {
        lsum += __shfl_down_sync(0xffffffffu, lsum, off);
        lsq  += __shfl_down_sync(0xffffffffu, lsq,  off);
    }
    if ((tid & 31) == 0) {
        atomicAdd(&g_stats[b * 2 + 0], lsum);
        atomicAdd(&g_stats[b * 2 + 1], lsq);
    }
}

// ---------------- kernel: groupnorm normalize (in place) -----------------
__global__ void __launch_bounds__(256) k_norm(
    const float* __restrict__ gamma, const float* __restrict__ beta,
    float* __restrict__ out)
{
    size_t idx = ((size_t)blockIdx.x * 256 + threadIdx.x) * 4;
    int b = (int)(idx >> 20);
    int c = (int)((idx >> 12) & 255);
    float s1 = g_stats[b * 2 + 0];
    float s2 = g_stats[b * 2 + 1];
    float mu  = s1 * (1.f / NEL_F);
    float var = s2 * (1.f / NEL_F) - mu * mu;
    float rs = rsqrtf(var + GN_EPS);
    float gm = gamma[c] * rs;
    float bb = beta[c] - mu * gm;
    float4 v = *(const float4*)&out[idx];
    v.x = v.x * gm + bb;
    v.y = v.y * gm + bb;
    v.z = v.z * gm + bb;
    v.w = v.w * gm + bb;
    *(float4*)&out[idx] = v;
}

// ---------------- launch ----------------
extern "C" void kernel_launch(void* const* d_in, const int* in_sizes, int n_in,
                              void* d_out, int out_size)
{
    const float* x     = (const float*)d_in[0];
    const float* Wqkv  = (const float*)d_in[1];
    const float* bqkv  = (const float*)d_in[2];
    const float* Wout  = (const float*)d_in[3];
    const float* bout  = (const float*)d_in[4];
    const float* gamma = (const float*)d_in[5];
    const float* beta  = (const float*)d_in[6];
    float* out = (float*)d_out;

    static bool attr_done = false;
    if (!attr_done) {
        cudaFuncSetAttribute(k_qkv_mma,  cudaFuncAttributeMaxDynamicSharedMemorySize, SMEM_BYTES);
        cudaFuncSetAttribute(k_proj_mma, cudaFuncAttributeMaxDynamicSharedMemorySize, SMEM_BYTES);
        attr_done = true;
    }

    k_conv <<<dim3(32, 8, 32), 128>>>(x);
    k_wconv<<<512, 256>>>(Wqkv);
    k_qkv_mma <<<dim3(32, 3, 32), 256, SMEM_BYTES>>>(bqkv);
    k_ctx  <<<dim3(128, 16), 64>>>();
    k_wp   <<<dim3(32, 8), 256>>>(Wout);
    k_proj_mma<<<dim3(32, 2, 32), 256, SMEM_BYTES>>>(bout, out);
    k_norm <<<32768, 256>>>(gamma, beta, out);
}

// round 13
// speedup vs baseline: 1.2620x; 1.0708x over previous
#include <cuda_runtime.h>
#include <cuda_fp16.h>
#include <cstdint>

// ---------------- problem constants ----------------
#define BATCH   32
#define CIN     256
#define NPIX    4096
#define HID     128
#define HEADS   4
#define DH      32
#define QSCALE  0.17677669529663687f
#define GN_EPS  1e-5f
#define NEL_F   1048576.0f

// ---------------- scratch (device globals; no runtime alloc) -------------
__device__ __half g_xth[(size_t)BATCH * NPIX * CIN];   // x^T hi [b][n][c]
__device__ __half g_xtl[(size_t)BATCH * NPIX * CIN];   // x^T lo
__device__ __half g_wqh[384 * CIN];                    // Wqkv fp16 [o][c]
__device__ __half g_qh[(size_t)BATCH * NPIX * HID];    // q' hi [b][n][c]
__device__ __half g_ql[(size_t)BATCH * NPIX * HID];    // q' lo
__device__ float g_k[(size_t)BATCH * HID * NPIX];
__device__ float g_v[(size_t)BATCH * HID * NPIX];
__device__ float g_ctx[BATCH * HEADS * DH * DH];
__device__ __half g_wph[BATCH * 256 * HID];            // W' fp16 [b][o][c]
__device__ float g_stats[BATCH * 2];

// ---------------- helpers ----------------
__device__ __forceinline__ uint32_t s2u(const void* p) {
    uint32_t a;
    asm("{ .reg .u64 t; cvta.to.shared.u64 t, %1; cvt.u32.u64 %0, t; }" : "=r"(a) : "l"(p));
    return a;
}
__device__ __forceinline__ uint32_t pack_h(__half a, __half b) {
    return (uint32_t)__half_as_ushort(a) | ((uint32_t)__half_as_ushort(b) << 16);
}
__device__ __forceinline__ void split_h(float x, __half& h, __half& l) {
    h = __float2half(x);
    l = __float2half(x - __half2float(h));
}

__device__ __forceinline__ void mma_f16(float d[4],
    uint32_t a0, uint32_t a1, uint32_t a2, uint32_t a3,
    uint32_t b0, uint32_t b1)
{
    asm("mma.sync.aligned.m16n8k16.row.col.f32.f16.f16.f32 "
        "{%0,%1,%2,%3}, {%4,%5,%6,%7}, {%8,%9}, {%0,%1,%2,%3};"
        : "+f"(d[0]), "+f"(d[1]), "+f"(d[2]), "+f"(d[3])
        : "r"(a0), "r"(a1), "r"(a2), "r"(a3), "r"(b0), "r"(b1));
}
__device__ __forceinline__ void ldsm4(uint32_t r[4], uint32_t addr) {
    asm volatile("ldmatrix.sync.aligned.m8n8.x4.shared.b16 {%0,%1,%2,%3}, [%4];"
        : "=r"(r[0]), "=r"(r[1]), "=r"(r[2]), "=r"(r[3]) : "r"(addr));
}
#define CPA(dst, src) asm volatile("cp.async.cg.shared.global [%0], [%1], 16;" :: "r"(dst), "l"(src))
#define CPC()  asm volatile("cp.async.commit_group;" ::: "memory")
#define CPW0() asm volatile("cp.async.wait_group 0;" ::: "memory")
#define CPW1() asm volatile("cp.async.wait_group 1;" ::: "memory")

// ---------------- GEMM core: fp16, NBL B-terms (1 or 2) ------------------
// Block tile M=128 x N=128; D = A(fp16) . (Bh [+ Bl])^T, fp32 accum.
#define ARR_B  (128 * 64)                   // 8192 bytes per array
#define STAGE1 (3 * ARR_B)                  // 24576 per stage (slot for 3 arrays)
#define SROW 129
#define S_BYTES (128 * SROW * 4)            // 66048 (aliases stage area)
#define BIAS_OFF (3 * STAGE1)               // 73728
#define SMEM_BYTES (BIAS_OFF + 512)         // 74240

__device__ __forceinline__ uint32_t swadr(uint32_t sb, int arr, int row, int seg) {
    return sb + arr * ARR_B + row * 64 + (((uint32_t)(seg ^ ((row >> 1) & 3))) << 4);
}

template<int NBL>
__device__ __forceinline__ void stage_issue(
    uint32_t sb,
    const __half* __restrict__ A, int lda,
    const __half* __restrict__ Bh, const __half* __restrict__ Bl, int ldb,
    int kc)
{
    const int tid = threadIdx.x;
    const __half* gs[3] = {A, Bh, Bl};
    #pragma unroll
    for (int j = 0; j < 2 * (1 + NBL); j++) {
        const int arr = j >> 1;
        const int ld  = (arr == 0) ? lda : ldb;
        const int idx = tid + (j & 1) * 256;     // 0..511
        const int r   = idx >> 2;
        const int s   = idx & 3;
        const __half* src = gs[arr] + (size_t)r * ld + kc + s * 8;
        CPA(swadr(sb, arr, r, s), src);
    }
    CPC();
}

template<int NBL>
__device__ __forceinline__ void chunk_compute(uint32_t sb, float acc[4][4][4]) {
    const int lane = threadIdx.x & 31;
    const int wid  = threadIdx.x >> 5;
    const int wm   = (wid >> 2) * 64;
    const int wn   = (wid & 3) * 32;
    const int ra   = lane & 15;
    const int sa   = lane >> 4;
    const int rb   = ((lane >> 4) & 1) * 8 + (lane & 7);
    const int sbg  = (lane >> 3) & 1;

    uint32_t aad[4], bad[2][2];
    #pragma unroll
    for (int mt = 0; mt < 4; mt++)
        aad[mt] = swadr(sb, 0, wm + mt * 16 + ra, sa);
    #pragma unroll
    for (int pr = 0; pr < 2; pr++) {
        int row = wn + pr * 16 + rb;
        bad[pr][0] = swadr(sb, 1, row, sbg);
        if (NBL == 2) bad[pr][1] = swadr(sb, 2, row, sbg);
    }

    #pragma unroll
    for (int ks = 0; ks < 2; ks++) {
        const uint32_t xr = ks ? 0x20u : 0u;
        uint32_t ah[4][4], bh[2][4], bl[2][4];
        #pragma unroll
        for (int mt = 0; mt < 4; mt++)
            ldsm4(ah[mt], aad[mt] ^ xr);
        #pragma unroll
        for (int pr = 0; pr < 2; pr++) {
            ldsm4(bh[pr], bad[pr][0] ^ xr);
            if (NBL == 2) ldsm4(bl[pr], bad[pr][1] ^ xr);
        }
        #pragma unroll
        for (int mt = 0; mt < 4; mt++)
            #pragma unroll
            for (int nt = 0; nt < 4; nt++) {
                uint32_t b0h = bh[nt >> 1][(nt & 1) * 2], b1h = bh[nt >> 1][(nt & 1) * 2 + 1];
                mma_f16(acc[mt][nt], ah[mt][0], ah[mt][1], ah[mt][2], ah[mt][3], b0h, b1h);
                if (NBL == 2) {
                    uint32_t b0l = bl[nt >> 1][(nt & 1) * 2], b1l = bl[nt >> 1][(nt & 1) * 2 + 1];
                    mma_f16(acc[mt][nt], ah[mt][0], ah[mt][1], ah[mt][2], ah[mt][3], b0l, b1l);
                }
            }
    }
}

template<int KTOT, int NBL>
__device__ __forceinline__ void gemm_block(
    const __half* __restrict__ A, int lda,
    const __half* __restrict__ Bh, const __half* __restrict__ Bl, int ldb,
    uint32_t sbase, float acc[4][4][4])
{
    constexpr int NCHUNK = KTOT / 32;
    stage_issue<NBL>(sbase, A, lda, Bh, Bl, ldb, 0);
    if (NCHUNK > 1) stage_issue<NBL>(sbase + STAGE1, A, lda, Bh, Bl, ldb, 32);
    #pragma unroll 1
    for (int c = 0; c < NCHUNK; c++) {
        if (c + 1 < NCHUNK) { CPW1(); } else { CPW0(); }
        __syncthreads();
        if (c + 2 < NCHUNK) {
            const uint32_t nbuf = sbase + ((c + 2) % 3) * STAGE1;
            stage_issue<NBL>(nbuf, A, lda, Bh, Bl, ldb, (c + 2) * 32);
        }
        chunk_compute<NBL>(sbase + (c % 3) * STAGE1, acc);
    }
    __syncthreads();
}

__device__ __forceinline__ void acc_to_smem(float* S, float acc[4][4][4]) {
    const int lane = threadIdx.x & 31;
    const int wid  = threadIdx.x >> 5;
    const int wm   = (wid >> 2) * 64;
    const int wn   = (wid & 3) * 32;
    #pragma unroll
    for (int mt = 0; mt < 4; mt++)
        #pragma unroll
        for (int nt = 0; nt < 4; nt++) {
            int r = wm + mt * 16 + (lane >> 2);
            int c = wn + nt * 8 + (lane & 3) * 2;
            S[r * SROW + c]           = acc[mt][nt][0];
            S[r * SROW + c + 1]       = acc[mt][nt][1];
            S[(r + 8) * SROW + c]     = acc[mt][nt][2];
            S[(r + 8) * SROW + c + 1] = acc[mt][nt][3];
        }
    __syncthreads();
}

// ---------------- kernel: transpose + fp16 split of x --------------------
__global__ void __launch_bounds__(128) k_conv(const float* __restrict__ x) {
    __shared__ float s[32][129];
    const int tid = threadIdx.x;
    const int n0 = blockIdx.x * 128;
    const int c0 = blockIdx.y * 32;
    const int b  = blockIdx.z;

    #pragma unroll
    for (int cc = 0; cc < 32; cc++)
        s[cc][tid] = x[((size_t)b * CIN + c0 + cc) * NPIX + n0 + tid];
    __syncthreads();

    uint32_t pkh[16], pkl[16];
    #pragma unroll
    for (int cc = 0; cc < 32; cc += 2) {
        __half h0, l0, h1, l1;
        split_h(s[cc][tid], h0, l0);
        split_h(s[cc + 1][tid], h1, l1);
        pkh[cc >> 1] = pack_h(h0, h1);
        pkl[cc >> 1] = pack_h(l0, l1);
    }
    const size_t eb = ((size_t)b * NPIX + n0 + tid) * CIN + c0;
    uint4* dh = (uint4*)&g_xth[eb];
    uint4* dl = (uint4*)&g_xtl[eb];
    #pragma unroll
    for (int q = 0; q < 4; q++) {
        dh[q] = make_uint4(pkh[q*4], pkh[q*4+1], pkh[q*4+2], pkh[q*4+3]);
        dl[q] = make_uint4(pkl[q*4], pkl[q*4+1], pkl[q*4+2], pkl[q*4+3]);
    }
}

// ---------------- kernel: fp16 convert Wqkv + zero accumulators ----------
__global__ void k_wconv(const float* __restrict__ W) {
    int i = blockIdx.x * 256 + threadIdx.x;
    if (i < 384 * CIN) g_wqh[i] = __float2half(W[i]);
    if (i < BATCH * HEADS * DH * DH) g_ctx[i] = 0.f;
    if (i < BATCH * 2) g_stats[i] = 0.f;
}

// ---------------- kernel: QKV GEMM + softmax epilogue --------------------
// m=0 (q): 2-term B (xh+xl).  m=1,2 (k,v): 1-term B (xh) — errors average
// out in the ctx reduction over 4096 pixels.
__global__ void __launch_bounds__(256, 2) k_qkv_mma(const float* __restrict__ bqkv)
{
    extern __shared__ char smem[];
    const uint32_t sbase = s2u(smem);
    float* S = (float*)smem;
    float* bias_s = (float*)(smem + BIAS_OFF);
    const int tid = threadIdx.x;
    const int n0 = blockIdx.x * 128;
    const int m  = blockIdx.y;
    const int b  = blockIdx.z;

    if (tid < 128) bias_s[tid] = bqkv[m * 128 + tid];

    float acc[4][4][4];
    #pragma unroll
    for (int i = 0; i < 4; i++)
        #pragma unroll
        for (int j = 0; j < 4; j++)
            #pragma unroll
            for (int q = 0; q < 4; q++) acc[i][j][q] = 0.f;

    const __half* A  = g_wqh + m * 128 * CIN;
    const __half* Bh = g_xth + ((size_t)b * NPIX + n0) * CIN;
    const __half* Bl = g_xtl + ((size_t)b * NPIX + n0) * CIN;
    if (m == 0)
        gemm_block<CIN, 2>(A, CIN, Bh, Bl, CIN, sbase, acc);
    else
        gemm_block<CIN, 1>(A, CIN, Bh, Bl, CIN, sbase, acc);
    acc_to_smem(S, acc);

    const int col = tid & 127;
    const int half = tid >> 7;
    const int pixel = n0 + col;

    if (m == 2) {
        #pragma unroll 4
        for (int r = half * 64; r < half * 64 + 64; r++)
            g_v[((size_t)b * HID + r) * NPIX + pixel] = S[r * SROW + col] + bias_s[r];
        return;
    }
    #pragma unroll
    for (int g = 0; g < 2; g++) {
        const int rb = half * 64 + g * 32;
        float v[32];
        float mx = -1e30f;
        #pragma unroll
        for (int j = 0; j < 32; j++) {
            v[j] = S[(rb + j) * SROW + col] + bias_s[rb + j];
            mx = fmaxf(mx, v[j]);
        }
        float s = 0.f;
        #pragma unroll
        for (int j = 0; j < 32; j++) { v[j] = __expf(v[j] - mx); s += v[j]; }
        float inv = 1.f / s;
        if (m == 0) inv *= QSCALE;
        if (m == 1) {
            #pragma unroll
            for (int j = 0; j < 32; j++)
                g_k[((size_t)b * HID + rb + j) * NPIX + pixel] = v[j] * inv;
        } else {
            uint32_t pkh[16], pkl[16];
            #pragma unroll
            for (int j = 0; j < 32; j += 2) {
                __half h0, l0, h1, l1;
                split_h(v[j] * inv, h0, l0);
                split_h(v[j + 1] * inv, h1, l1);
                pkh[j >> 1] = pack_h(h0, h1);
                pkl[j >> 1] = pack_h(l0, l1);
            }
            size_t e = ((size_t)b * NPIX + pixel) * HID + rb;
            uint4* dh = (uint4*)&g_qh[e];
            uint4* dl = (uint4*)&g_ql[e];
            #pragma unroll
            for (int q = 0; q < 4; q++) {
                dh[q] = make_uint4(pkh[q*4], pkh[q*4+1], pkh[q*4+2], pkh[q*4+3]);
                dl[q] = make_uint4(pkl[q*4], pkl[q*4+1], pkl[q*4+2], pkl[q*4+3]);
            }
        }
    }
}

// ---------------- kernel: context[b,h,d,e] = sum_n k'[d,n] v[e,n] --------
__global__ void __launch_bounds__(64) k_ctx()
{
    __shared__ float Ks[32][65];
    __shared__ float Vs[32][65];

    const int bh = blockIdx.x;
    const int seg = blockIdx.y;
    const int b = bh >> 2, h = bh & 3;
    const int tid = threadIdx.x;
    const int d0 = (tid >> 3) * 4;
    const int e0 = (tid & 7) * 4;

    float acc[4][4];
    #pragma unroll
    for (int i = 0; i < 4; i++)
        #pragma unroll
        for (int j = 0; j < 4; j++) acc[i][j] = 0.f;

    const float* kp = g_k + ((size_t)b * HID + h * DH) * NPIX + seg * 256;
    const float* vp = g_v + ((size_t)b * HID + h * DH) * NPIX + seg * 256;

    #pragma unroll 1
    for (int c0 = 0; c0 < 256; c0 += 64) {
        __syncthreads();
        #pragma unroll
        for (int i = 0; i < 32; i++) {
            Ks[i][tid] = kp[(size_t)i * NPIX + c0 + tid];
            Vs[i][tid] = vp[(size_t)i * NPIX + c0 + tid];
        }
        __syncthreads();
        #pragma unroll 4
        for (int nn = 0; nn < 64; nn++) {
            float ka[4], va[4];
            #pragma unroll
            for (int i = 0; i < 4; i++) ka[i] = Ks[d0 + i][nn];
            #pragma unroll
            for (int j = 0; j < 4; j++) va[j] = Vs[e0 + j][nn];
            #pragma unroll
            for (int i = 0; i < 4; i++)
                #pragma unroll
                for (int j = 0; j < 4; j++)
                    acc[i][j] += ka[i] * va[j];
        }
    }
    float* cdst = g_ctx + ((b * HEADS + h) * DH + d0) * DH + e0;
    #pragma unroll
    for (int i = 0; i < 4; i++)
        #pragma unroll
        for (int j = 0; j < 4; j++)
            atomicAdd(cdst + i * DH + j, acc[i][j]);
}

// ---------------- kernel: fold Wout with context -> fp16 -----------------
__global__ void __launch_bounds__(256) k_wp(const float* __restrict__ Wout)
{
    __shared__ float ctxs[HEADS * DH * 33];
    const int b = blockIdx.x;
    const int obase = blockIdx.y * 32;

    for (int i = threadIdx.x; i < HEADS * DH * DH; i += 256)
        ctxs[(i >> 5) * 33 + (i & 31)] = g_ctx[b * HEADS * DH * DH + i];
    __syncthreads();

    int hd = threadIdx.x & 127;
    int hb = hd & 0xE0;
    for (int oi = threadIdx.x >> 7; oi < 32; oi += 2) {
        int o = obase + oi;
        float s = 0.f;
        #pragma unroll
        for (int e = 0; e < 32; e++)
            s += Wout[o * HID + hb + e] * ctxs[hd * 33 + e];
        g_wph[((size_t)b * 256 + o) * HID + hd] = __float2half(s);
    }
}

// ---------------- kernel: projection GEMM + GN stats ---------------------
__global__ void __launch_bounds__(256, 2) k_proj_mma(
    const float* __restrict__ bout, float* __restrict__ out)
{
    extern __shared__ char smem[];
    const uint32_t sbase = s2u(smem);
    float* S = (float*)smem;
    float* bias_s = (float*)(smem + BIAS_OFF);
    const int tid = threadIdx.x;
    const int n0 = blockIdx.x * 128;
    const int o0 = blockIdx.y * 128;
    const int b  = blockIdx.z;

    if (tid < 128) bias_s[tid] = bout[o0 + tid];

    float acc[4][4][4];
    #pragma unroll
    for (int i = 0; i < 4; i++)
        #pragma unroll
        for (int j = 0; j < 4; j++)
            #pragma unroll
            for (int q = 0; q < 4; q++) acc[i][j][q] = 0.f;

    gemm_block<HID, 2>(g_wph + ((size_t)b * 256 + o0) * HID, HID,
                       g_qh + ((size_t)b * NPIX + n0) * HID,
                       g_ql + ((size_t)b * NPIX + n0) * HID, HID,
                       sbase, acc);
    acc_to_smem(S, acc);

    const int col = tid & 127;
    const int half = tid >> 7;
    const int pixel = n0 + col;
    float lsum = 0.f, lsq = 0.f;

    #pragma unroll 4
    for (int r = half * 64; r < half * 64 + 64; r++) {
        float val = S[r * SROW + col] + bias_s[r];
        lsum += val;
        lsq  += val * val;
        out[((size_t)b * 256 + o0 + r) * NPIX + pixel] = val;
    }
    #pragma unroll
    for (int off = 16; off > 0; off >>= 1) {
        lsum += __shfl_down_sync(0xffffffffu, lsum, off);
        lsq  += __shfl_down_sync(0xffffffffu, lsq,  off);
    }
    if ((tid & 31) == 0) {
        atomicAdd(&g_stats[b * 2 + 0], lsum);
        atomicAdd(&g_stats[b * 2 + 1], lsq);
    }
}

// ---------------- kernel: groupnorm normalize (in place) -----------------
__global__ void __launch_bounds__(256) k_norm(
    const float* __restrict__ gamma, const float* __restrict__ beta,
    float* __restrict__ out)
{
    size_t idx = ((size_t)blockIdx.x * 256 + threadIdx.x) * 4;
    int b = (int)(idx >> 20);
    int c = (int)((idx >> 12) & 255);
    float s1 = g_stats[b * 2 + 0];
    float s2 = g_stats[b * 2 + 1];
    float mu  = s1 * (1.f / NEL_F);
    float var = s2 * (1.f / NEL_F) - mu * mu;
    float rs = rsqrtf(var + GN_EPS);
    float gm = gamma[c] * rs;
    float bb = beta[c] - mu * gm;
    float4 v = *(const float4*)&out[idx];
    v.x = v.x * gm + bb;
    v.y = v.y * gm + bb;
    v.z = v.z * gm + bb;
    v.w = v.w * gm + bb;
    *(float4*)&out[idx] = v;
}

// ---------------- launch ----------------
extern "C" void kernel_launch(void* const* d_in, const int* in_sizes, int n_in,
                              void* d_out, int out_size)
{
    const float* x     = (const float*)d_in[0];
    const float* Wqkv  = (const float*)d_in[1];
    const float* bqkv  = (const float*)d_in[2];
    const float* Wout  = (const float*)d_in[3];
    const float* bout  = (const float*)d_in[4];
    const float* gamma = (const float*)d_in[5];
    const float* beta  = (const float*)d_in[6];
    float* out = (float*)d_out;

    static bool attr_done = false;
    if (!attr_done) {
        cudaFuncSetAttribute(k_qkv_mma,  cudaFuncAttributeMaxDynamicSharedMemorySize, SMEM_BYTES);
        cudaFuncSetAttribute(k_proj_mma, cudaFuncAttributeMaxDynamicSharedMemorySize, SMEM_BYTES);
        attr_done = true;
    }

    k_conv <<<dim3(32, 8, 32), 128>>>(x);
    k_wconv<<<512, 256>>>(Wqkv);
    k_qkv_mma <<<dim3(32, 3, 32), 256, SMEM_BYTES>>>(bqkv);
    k_ctx  <<<dim3(128, 16), 64>>>();
    k_wp   <<<dim3(32, 8), 256>>>(Wout);
    k_proj_mma<<<dim3(32, 2, 32), 256, SMEM_BYTES>>>(bout, out);
    k_norm <<<32768, 256>>>(gamma, beta, out);
}

// round 14
// speedup vs baseline: 1.4947x; 1.1844x over previous
#include <cuda_runtime.h>
#include <cuda_fp16.h>
#include <cstdint>

// ---------------- problem constants ----------------
#define BATCH   32
#define CIN     256
#define NPIX    4096
#define HID     128
#define HEADS   4
#define DH      32
#define QSCALE  0.17677669529663687f
#define GN_EPS  1e-5f
#define NEL_F   1048576.0f

// ---------------- scratch (device globals; no runtime alloc) -------------
__device__ __half g_xt [(size_t)BATCH * NPIX * CIN];   // x^T fp16 [b][n][c]
__device__ __half g_wq [384 * CIN];                    // Wqkv fp16 [o][c]
__device__ __half g_q  [(size_t)BATCH * NPIX * HID];   // q' fp16 [b][n][c]
__device__ float g_k[(size_t)BATCH * HID * NPIX];
__device__ float g_v[(size_t)BATCH * HID * NPIX];
__device__ float g_ctx[BATCH * HEADS * DH * DH];
__device__ __half g_wp [BATCH * 256 * HID];            // W' fp16 [b][o][c]
__device__ float g_stats[BATCH * 2];

// ---------------- helpers ----------------
__device__ __forceinline__ uint32_t s2u(const void* p) {
    uint32_t a;
    asm("{ .reg .u64 t; cvta.to.shared.u64 t, %1; cvt.u32.u64 %0, t; }" : "=r"(a) : "l"(p));
    return a;
}
__device__ __forceinline__ uint32_t pack_h(__half a, __half b) {
    return (uint32_t)__half_as_ushort(a) | ((uint32_t)__half_as_ushort(b) << 16);
}

__device__ __forceinline__ void mma_f16(float d[4],
    uint32_t a0, uint32_t a1, uint32_t a2, uint32_t a3,
    uint32_t b0, uint32_t b1)
{
    asm("mma.sync.aligned.m16n8k16.row.col.f32.f16.f16.f32 "
        "{%0,%1,%2,%3}, {%4,%5,%6,%7}, {%8,%9}, {%0,%1,%2,%3};"
        : "+f"(d[0]), "+f"(d[1]), "+f"(d[2]), "+f"(d[3])
        : "r"(a0), "r"(a1), "r"(a2), "r"(a3), "r"(b0), "r"(b1));
}
__device__ __forceinline__ void ldsm4(uint32_t r[4], uint32_t addr) {
    asm volatile("ldmatrix.sync.aligned.m8n8.x4.shared.b16 {%0,%1,%2,%3}, [%4];"
        : "=r"(r[0]), "=r"(r[1]), "=r"(r[2]), "=r"(r[3]) : "r"(addr));
}
#define CPA(dst, src) asm volatile("cp.async.cg.shared.global [%0], [%1], 16;" :: "r"(dst), "l"(src))
#define CPC()  asm volatile("cp.async.commit_group;" ::: "memory")
#define CPW0() asm volatile("cp.async.wait_group 0;" ::: "memory")
#define CPW1() asm volatile("cp.async.wait_group 1;" ::: "memory")

// ---------------- GEMM core: plain fp16, fp32 accum ----------------------
// Block tile M=128 x N=128; D = A . B^T. Stage = 2 arrays (A, B) of 8 KB.
// 3 buffers, 2 cp.async groups in flight, one sync per chunk.
#define ARR_B  (128 * 64)                   // 8192 bytes per array
#define STAGE1 (2 * ARR_B)                  // 16384 per stage
#define SROW 129
#define S_BYTES (128 * SROW * 4)            // 66048 (aliases stage area)
#define BIAS_OFF 66048
#define SMEM_BYTES (BIAS_OFF + 512)         // 66560

__device__ __forceinline__ uint32_t swadr(uint32_t sb, int arr, int row, int seg) {
    return sb + arr * ARR_B + row * 64 + (((uint32_t)(seg ^ ((row >> 1) & 3))) << 4);
}

__device__ __forceinline__ void stage_issue(
    uint32_t sb,
    const __half* __restrict__ A, int lda,
    const __half* __restrict__ B, int ldb,
    int kc)
{
    const int tid = threadIdx.x;
    const __half* gs[2] = {A, B};
    #pragma unroll
    for (int j = 0; j < 4; j++) {
        const int arr = j >> 1;
        const int ld  = (arr == 0) ? lda : ldb;
        const int idx = tid + (j & 1) * 256;     // 0..511
        const int r   = idx >> 2;
        const int s   = idx & 3;
        const __half* src = gs[arr] + (size_t)r * ld + kc + s * 8;
        CPA(swadr(sb, arr, r, s), src);
    }
    CPC();
}

__device__ __forceinline__ void chunk_compute(uint32_t sb, float acc[4][4][4]) {
    const int lane = threadIdx.x & 31;
    const int wid  = threadIdx.x >> 5;
    const int wm   = (wid >> 2) * 64;
    const int wn   = (wid & 3) * 32;
    const int ra   = lane & 15;
    const int sa   = lane >> 4;
    const int rb   = ((lane >> 4) & 1) * 8 + (lane & 7);
    const int sbg  = (lane >> 3) & 1;

    uint32_t aad[4], bad[2];
    #pragma unroll
    for (int mt = 0; mt < 4; mt++)
        aad[mt] = swadr(sb, 0, wm + mt * 16 + ra, sa);
    #pragma unroll
    for (int pr = 0; pr < 2; pr++)
        bad[pr] = swadr(sb, 1, wn + pr * 16 + rb, sbg);

    #pragma unroll
    for (int ks = 0; ks < 2; ks++) {
        const uint32_t xr = ks ? 0x20u : 0u;
        uint32_t ah[4][4], bh[2][4];
        #pragma unroll
        for (int mt = 0; mt < 4; mt++)
            ldsm4(ah[mt], aad[mt] ^ xr);
        #pragma unroll
        for (int pr = 0; pr < 2; pr++)
            ldsm4(bh[pr], bad[pr] ^ xr);
        #pragma unroll
        for (int mt = 0; mt < 4; mt++)
            #pragma unroll
            for (int nt = 0; nt < 4; nt++) {
                uint32_t b0 = bh[nt >> 1][(nt & 1) * 2], b1 = bh[nt >> 1][(nt & 1) * 2 + 1];
                mma_f16(acc[mt][nt], ah[mt][0], ah[mt][1], ah[mt][2], ah[mt][3], b0, b1);
            }
    }
}

template<int KTOT>
__device__ __forceinline__ void gemm_block(
    const __half* __restrict__ A, int lda,
    const __half* __restrict__ B, int ldb,
    uint32_t sbase, float acc[4][4][4])
{
    constexpr int NCHUNK = KTOT / 32;
    stage_issue(sbase, A, lda, B, ldb, 0);
    if (NCHUNK > 1) stage_issue(sbase + STAGE1, A, lda, B, ldb, 32);
    #pragma unroll 1
    for (int c = 0; c < NCHUNK; c++) {
        if (c + 1 < NCHUNK) { CPW1(); } else { CPW0(); }
        __syncthreads();
        if (c + 2 < NCHUNK) {
            const uint32_t nbuf = sbase + ((c + 2) % 3) * STAGE1;
            stage_issue(nbuf, A, lda, B, ldb, (c + 2) * 32);
        }
        chunk_compute(sbase + (c % 3) * STAGE1, acc);
    }
    __syncthreads();
}

__device__ __forceinline__ void acc_to_smem(float* S, float acc[4][4][4]) {
    const int lane = threadIdx.x & 31;
    const int wid  = threadIdx.x >> 5;
    const int wm   = (wid >> 2) * 64;
    const int wn   = (wid & 3) * 32;
    #pragma unroll
    for (int mt = 0; mt < 4; mt++)
        #pragma unroll
        for (int nt = 0; nt < 4; nt++) {
            int r = wm + mt * 16 + (lane >> 2);
            int c = wn + nt * 8 + (lane & 3) * 2;
            S[r * SROW + c]           = acc[mt][nt][0];
            S[r * SROW + c + 1]       = acc[mt][nt][1];
            S[(r + 8) * SROW + c]     = acc[mt][nt][2];
            S[(r + 8) * SROW + c + 1] = acc[mt][nt][3];
        }
    __syncthreads();
}

// ---------------- kernel: transpose + fp16 convert of x ------------------
__global__ void __launch_bounds__(128) k_conv(const float* __restrict__ x) {
    __shared__ float s[32][129];
    const int tid = threadIdx.x;
    const int n0 = blockIdx.x * 128;
    const int c0 = blockIdx.y * 32;
    const int b  = blockIdx.z;

    #pragma unroll
    for (int cc = 0; cc < 32; cc++)
        s[cc][tid] = x[((size_t)b * CIN + c0 + cc) * NPIX + n0 + tid];
    __syncthreads();

    uint32_t pk[16];
    #pragma unroll
    for (int cc = 0; cc < 32; cc += 2)
        pk[cc >> 1] = pack_h(__float2half(s[cc][tid]), __float2half(s[cc + 1][tid]));
    const size_t eb = ((size_t)b * NPIX + n0 + tid) * CIN + c0;
    uint4* d = (uint4*)&g_xt[eb];
    #pragma unroll
    for (int q = 0; q < 4; q++)
        d[q] = make_uint4(pk[q*4], pk[q*4+1], pk[q*4+2], pk[q*4+3]);
}

// ---------------- kernel: fp16 convert Wqkv + zero accumulators ----------
__global__ void k_wconv(const float* __restrict__ W) {
    int i = blockIdx.x * 256 + threadIdx.x;
    if (i < 384 * CIN) g_wq[i] = __float2half(W[i]);
    if (i < BATCH * HEADS * DH * DH) g_ctx[i] = 0.f;
    if (i < BATCH * 2) g_stats[i] = 0.f;
}

// ---------------- kernel: QKV GEMM + softmax epilogue --------------------
__global__ void __launch_bounds__(256, 2) k_qkv_mma(const float* __restrict__ bqkv)
{
    extern __shared__ char smem[];
    const uint32_t sbase = s2u(smem);
    float* S = (float*)smem;
    float* bias_s = (float*)(smem + BIAS_OFF);
    const int tid = threadIdx.x;
    const int n0 = blockIdx.x * 128;
    const int m  = blockIdx.y;
    const int b  = blockIdx.z;

    if (tid < 128) bias_s[tid] = bqkv[m * 128 + tid];

    float acc[4][4][4];
    #pragma unroll
    for (int i = 0; i < 4; i++)
        #pragma unroll
        for (int j = 0; j < 4; j++)
            #pragma unroll
            for (int q = 0; q < 4; q++) acc[i][j][q] = 0.f;

    gemm_block<CIN>(g_wq + m * 128 * CIN, CIN,
                    g_xt + ((size_t)b * NPIX + n0) * CIN, CIN,
                    sbase, acc);
    acc_to_smem(S, acc);

    const int col = tid & 127;
    const int half = tid >> 7;
    const int pixel = n0 + col;

    if (m == 2) {
        #pragma unroll 4
        for (int r = half * 64; r < half * 64 + 64; r++)
            g_v[((size_t)b * HID + r) * NPIX + pixel] = S[r * SROW + col] + bias_s[r];
        return;
    }
    #pragma unroll
    for (int g = 0; g < 2; g++) {
        const int rb = half * 64 + g * 32;
        float v[32];
        float mx = -1e30f;
        #pragma unroll
        for (int j = 0; j < 32; j++) {
            v[j] = S[(rb + j) * SROW + col] + bias_s[rb + j];
            mx = fmaxf(mx, v[j]);
        }
        float s = 0.f;
        #pragma unroll
        for (int j = 0; j < 32; j++) { v[j] = __expf(v[j] - mx); s += v[j]; }
        float inv = 1.f / s;
        if (m == 0) inv *= QSCALE;
        if (m == 1) {
            #pragma unroll
            for (int j = 0; j < 32; j++)
                g_k[((size_t)b * HID + rb + j) * NPIX + pixel] = v[j] * inv;
        } else {
            uint32_t pk[16];
            #pragma unroll
            for (int j = 0; j < 32; j += 2)
                pk[j >> 1] = pack_h(__float2half(v[j] * inv), __float2half(v[j + 1] * inv));
            size_t e = ((size_t)b * NPIX + pixel) * HID + rb;
            uint4* d = (uint4*)&g_q[e];
            #pragma unroll
            for (int q = 0; q < 4; q++)
                d[q] = make_uint4(pk[q*4], pk[q*4+1], pk[q*4+2], pk[q*4+3]);
        }
    }
}

// ---------------- kernel: context[b,h,d,e] = sum_n k'[d,n] v[e,n] --------
__global__ void __launch_bounds__(64) k_ctx()
{
    __shared__ float Ks[32][65];
    __shared__ float Vs[32][65];

    const int bh = blockIdx.x;
    const int seg = blockIdx.y;
    const int b = bh >> 2, h = bh & 3;
    const int tid = threadIdx.x;
    const int d0 = (tid >> 3) * 4;
    const int e0 = (tid & 7) * 4;

    float acc[4][4];
    #pragma unroll
    for (int i = 0; i < 4; i++)
        #pragma unroll
        for (int j = 0; j < 4; j++) acc[i][j] = 0.f;

    const float* kp = g_k + ((size_t)b * HID + h * DH) * NPIX + seg * 256;
    const float* vp = g_v + ((size_t)b * HID + h * DH) * NPIX + seg * 256;

    #pragma unroll 1
    for (int c0 = 0; c0 < 256; c0 += 64) {
        __syncthreads();
        #pragma unroll
        for (int i = 0; i < 32; i++) {
            Ks[i][tid] = kp[(size_t)i * NPIX + c0 + tid];
            Vs[i][tid] = vp[(size_t)i * NPIX + c0 + tid];
        }
        __syncthreads();
        #pragma unroll 4
        for (int nn = 0; nn < 64; nn++) {
            float ka[4], va[4];
            #pragma unroll
            for (int i = 0; i < 4; i++) ka[i] = Ks[d0 + i][nn];
            #pragma unroll
            for (int j = 0; j < 4; j++) va[j] = Vs[e0 + j][nn];
            #pragma unroll
            for (int i = 0; i < 4; i++)
                #pragma unroll
                for (int j = 0; j < 4; j++)
                    acc[i][j] += ka[i] * va[j];
        }
    }
    float* cdst = g_ctx + ((b * HEADS + h) * DH + d0) * DH + e0;
    #pragma unroll
    for (int i = 0; i < 4; i++)
        #pragma unroll
        for (int j = 0; j < 4; j++)
            atomicAdd(cdst + i * DH + j, acc[i][j]);
}

// ---------------- kernel: fold Wout with context -> fp16 -----------------
__global__ void __launch_bounds__(256) k_wp(const float* __restrict__ Wout)
{
    __shared__ float ctxs[HEADS * DH * 33];
    const int b = blockIdx.x;
    const int obase = blockIdx.y * 32;

    for (int i = threadIdx.x; i < HEADS * DH * DH; i += 256)
        ctxs[(i >> 5) * 33 + (i & 31)] = g_ctx[b * HEADS * DH * DH + i];
    __syncthreads();

    int hd = threadIdx.x & 127;
    int hb = hd & 0xE0;
    for (int oi = threadIdx.x >> 7; oi < 32; oi += 2) {
        int o = obase + oi;
        float s = 0.f;
        #pragma unroll
        for (int e = 0; e < 32; e++)
            s += Wout[o * HID + hb + e] * ctxs[hd * 33 + e];
        g_wp[((size_t)b * 256 + o) * HID + hd] = __float2half(s);
    }
}

// ---------------- kernel: projection GEMM + GN stats ---------------------
__global__ void __launch_bounds__(256, 2) k_proj_mma(
    const float* __restrict__ bout, float* __restrict__ out)
{
    extern __shared__ char smem[];
    const uint32_t sbase = s2u(smem);
    float* S = (float*)smem;
    float* bias_s = (float*)(smem + BIAS_OFF);
    const int tid = threadIdx.x;
    const int n0 = blockIdx.x * 128;
    const int o0 = blockIdx.y * 128;
    const int b  = blockIdx.z;

    if (tid < 128) bias_s[tid] = bout[o0 + tid];

    float acc[4][4][4];
    #pragma unroll
    for (int i = 0; i < 4; i++)
        #pragma unroll
        for (int j = 0; j < 4; j++)
            #pragma unroll
            for (int q = 0; q < 4; q++) acc[i][j][q] = 0.f;

    gemm_block<HID>(g_wp + ((size_t)b * 256 + o0) * HID, HID,
                    g_q + ((size_t)b * NPIX + n0) * HID, HID,
                    sbase, acc);
    acc_to_smem(S, acc);

    const int col = tid & 127;
    const int half = tid >> 7;
    const int pixel = n0 + col;
    float lsum = 0.f, lsq = 0.f;

    #pragma unroll 4
    for (int r = half * 64; r < half * 64 + 64; r++) {
        float val = S[r * SROW + col] + bias_s[r];
        lsum += val;
        lsq  += val * val;
        out[((size_t)b * 256 + o0 + r) * NPIX + pixel] = val;
    }
    #pragma unroll
    for (int off = 16; off > 0; off >>= 1) {
        lsum += __shfl_down_sync(0xffffffffu, lsum, off);
        lsq  += __shfl_down_sync(0xffffffffu, lsq,  off);
    }
    if ((tid & 31) == 0) {
        atomicAdd(&g_stats[b * 2 + 0], lsum);
        atomicAdd(&g_stats[b * 2 + 1], lsq);
    }
}

// ---------------- kernel: groupnorm normalize (in place) -----------------
__global__ void __launch_bounds__(256) k_norm(
    const float* __restrict__ gamma, const float* __restrict__ beta,
    float* __restrict__ out)
{
    size_t idx = ((size_t)blockIdx.x * 256 + threadIdx.x) * 4;
    int b = (int)(idx >> 20);
    int c = (int)((idx >> 12) & 255);
    float s1 = g_stats[b * 2 + 0];
    float s2 = g_stats[b * 2 + 1];
    float mu  = s1 * (1.f / NEL_F);
    float var = s2 * (1.f / NEL_F) - mu * mu;
    float rs = rsqrtf(var + GN_EPS);
    float gm = gamma[c] * rs;
    float bb = beta[c] - mu * gm;
    float4 v = *(const float4*)&out[idx];
    v.x = v.x * gm + bb;
    v.y = v.y * gm + bb;
    v.z = v.z * gm + bb;
    v.w = v.w * gm + bb;
    *(float4*)&out[idx] = v;
}

// ---------------- launch ----------------
extern "C" void kernel_launch(void* const* d_in, const int* in_sizes, int n_in,
                              void* d_out, int out_size)
{
    const float* x     = (const float*)d_in[0];
    const float* Wqkv  = (const float*)d_in[1];
    const float* bqkv  = (const float*)d_in[2];
    const float* Wout  = (const float*)d_in[3];
    const float* bout  = (const float*)d_in[4];
    const float* gamma = (const float*)d_in[5];
    const float* beta  = (const float*)d_in[6];
    float* out = (float*)d_out;

    static bool attr_done = false;
    if (!attr_done) {
        cudaFuncSetAttribute(k_qkv_mma,  cudaFuncAttributeMaxDynamicSharedMemorySize, SMEM_BYTES);
        cudaFuncSetAttribute(k_proj_mma, cudaFuncAttributeMaxDynamicSharedMemorySize, SMEM_BYTES);
        attr_done = true;
    }

    k_conv <<<dim3(32, 8, 32), 128>>>(x);
    k_wconv<<<512, 256>>>(Wqkv);
    k_qkv_mma <<<dim3(32, 3, 32), 256, SMEM_BYTES>>>(bqkv);
    k_ctx  <<<dim3(128, 16), 64>>>();
    k_wp   <<<dim3(32, 8), 256>>>(Wout);
    k_proj_mma<<<dim3(32, 2, 32), 256, SMEM_BYTES>>>(bout, out);
    k_norm <<<32768, 256>>>(gamma, beta, out);
}

// round 15
// speedup vs baseline: 1.5154x; 1.0139x over previous
#include <cuda_runtime.h>
#include <cuda_fp16.h>
#include <cstdint>

// ---------------- problem constants ----------------
#define BATCH   32
#define CIN     256
#define NPIX    4096
#define HID     128
#define HEADS   4
#define DH      32
#define QSCALE  0.17677669529663687f
#define GN_EPS  1e-5f
#define NEL_F   1048576.0f

// ---------------- scratch (device globals; no runtime alloc) -------------
__device__ __half g_xt [(size_t)BATCH * NPIX * CIN];   // x^T fp16 [b][n][c]
__device__ __half g_wq [384 * CIN];                    // Wqkv fp16 [o][c]
__device__ __half g_q  [(size_t)BATCH * NPIX * HID];   // q' fp16 [b][n][c]
__device__ __half g_k16[(size_t)BATCH * HID * NPIX];   // softmax(k) fp16 [b][c][n]
__device__ __half g_v16[(size_t)BATCH * HID * NPIX];   // v fp16 [b][c][n]
__device__ float g_ctx[BATCH * HEADS * DH * DH];
__device__ __half g_wp [BATCH * 256 * HID];            // W' fp16 [b][o][c]
__device__ float g_stats[BATCH * 2];

// ---------------- helpers ----------------
__device__ __forceinline__ uint32_t s2u(const void* p) {
    uint32_t a;
    asm("{ .reg .u64 t; cvta.to.shared.u64 t, %1; cvt.u32.u64 %0, t; }" : "=r"(a) : "l"(p));
    return a;
}
__device__ __forceinline__ uint32_t pack_h(__half a, __half b) {
    return (uint32_t)__half_as_ushort(a) | ((uint32_t)__half_as_ushort(b) << 16);
}

__device__ __forceinline__ void mma_f16(float d[4],
    uint32_t a0, uint32_t a1, uint32_t a2, uint32_t a3,
    uint32_t b0, uint32_t b1)
{
    asm("mma.sync.aligned.m16n8k16.row.col.f32.f16.f16.f32 "
        "{%0,%1,%2,%3}, {%4,%5,%6,%7}, {%8,%9}, {%0,%1,%2,%3};"
        : "+f"(d[0]), "+f"(d[1]), "+f"(d[2]), "+f"(d[3])
        : "r"(a0), "r"(a1), "r"(a2), "r"(a3), "r"(b0), "r"(b1));
}
__device__ __forceinline__ void ldsm4(uint32_t r[4], uint32_t addr) {
    asm volatile("ldmatrix.sync.aligned.m8n8.x4.shared.b16 {%0,%1,%2,%3}, [%4];"
        : "=r"(r[0]), "=r"(r[1]), "=r"(r[2]), "=r"(r[3]) : "r"(addr));
}
#define CPA(dst, src) asm volatile("cp.async.cg.shared.global [%0], [%1], 16;" :: "r"(dst), "l"(src))
#define CPC()  asm volatile("cp.async.commit_group;" ::: "memory")
#define CPW0() asm volatile("cp.async.wait_group 0;" ::: "memory")
#define CPW1() asm volatile("cp.async.wait_group 1;" ::: "memory")

// ---------------- GEMM core: plain fp16, fp32 accum ----------------------
#define ARR_B  (128 * 64)                   // 8192 bytes per array
#define STAGE1 (2 * ARR_B)                  // 16384 per stage
#define SROW 129
#define S_BYTES (128 * SROW * 4)            // 66048 (aliases stage area)
#define BIAS_OFF 66048
#define SMEM_BYTES (BIAS_OFF + 512)         // 66560

__device__ __forceinline__ uint32_t swadr(uint32_t sb, int arr, int row, int seg) {
    return sb + arr * ARR_B + row * 64 + (((uint32_t)(seg ^ ((row >> 1) & 3))) << 4);
}

__device__ __forceinline__ void stage_issue(
    uint32_t sb,
    const __half* __restrict__ A, int lda,
    const __half* __restrict__ B, int ldb,
    int kc)
{
    const int tid = threadIdx.x;
    const __half* gs[2] = {A, B};
    #pragma unroll
    for (int j = 0; j < 4; j++) {
        const int arr = j >> 1;
        const int ld  = (arr == 0) ? lda : ldb;
        const int idx = tid + (j & 1) * 256;     // 0..511
        const int r   = idx >> 2;
        const int s   = idx & 3;
        const __half* src = gs[arr] + (size_t)r * ld + kc + s * 8;
        CPA(swadr(sb, arr, r, s), src);
    }
    CPC();
}

__device__ __forceinline__ void chunk_compute(uint32_t sb, float acc[4][4][4]) {
    const int lane = threadIdx.x & 31;
    const int wid  = threadIdx.x >> 5;
    const int wm   = (wid >> 2) * 64;
    const int wn   = (wid & 3) * 32;
    const int ra   = lane & 15;
    const int sa   = lane >> 4;
    const int rb   = ((lane >> 4) & 1) * 8 + (lane & 7);
    const int sbg  = (lane >> 3) & 1;

    uint32_t aad[4], bad[2];
    #pragma unroll
    for (int mt = 0; mt < 4; mt++)
        aad[mt] = swadr(sb, 0, wm + mt * 16 + ra, sa);
    #pragma unroll
    for (int pr = 0; pr < 2; pr++)
        bad[pr] = swadr(sb, 1, wn + pr * 16 + rb, sbg);

    #pragma unroll
    for (int ks = 0; ks < 2; ks++) {
        const uint32_t xr = ks ? 0x20u : 0u;
        uint32_t ah[4][4], bh[2][4];
        #pragma unroll
        for (int mt = 0; mt < 4; mt++)
            ldsm4(ah[mt], aad[mt] ^ xr);
        #pragma unroll
        for (int pr = 0; pr < 2; pr++)
            ldsm4(bh[pr], bad[pr] ^ xr);
        #pragma unroll
        for (int mt = 0; mt < 4; mt++)
            #pragma unroll
            for (int nt = 0; nt < 4; nt++) {
                uint32_t b0 = bh[nt >> 1][(nt & 1) * 2], b1 = bh[nt >> 1][(nt & 1) * 2 + 1];
                mma_f16(acc[mt][nt], ah[mt][0], ah[mt][1], ah[mt][2], ah[mt][3], b0, b1);
            }
    }
}

template<int KTOT>
__device__ __forceinline__ void gemm_block(
    const __half* __restrict__ A, int lda,
    const __half* __restrict__ B, int ldb,
    uint32_t sbase, float acc[4][4][4])
{
    constexpr int NCHUNK = KTOT / 32;
    stage_issue(sbase, A, lda, B, ldb, 0);
    if (NCHUNK > 1) stage_issue(sbase + STAGE1, A, lda, B, ldb, 32);
    #pragma unroll 1
    for (int c = 0; c < NCHUNK; c++) {
        if (c + 1 < NCHUNK) { CPW1(); } else { CPW0(); }
        __syncthreads();
        if (c + 2 < NCHUNK) {
            const uint32_t nbuf = sbase + ((c + 2) % 3) * STAGE1;
            stage_issue(nbuf, A, lda, B, ldb, (c + 2) * 32);
        }
        chunk_compute(sbase + (c % 3) * STAGE1, acc);
    }
    __syncthreads();
}

__device__ __forceinline__ void acc_to_smem(float* S, float acc[4][4][4]) {
    const int lane = threadIdx.x & 31;
    const int wid  = threadIdx.x >> 5;
    const int wm   = (wid >> 2) * 64;
    const int wn   = (wid & 3) * 32;
    #pragma unroll
    for (int mt = 0; mt < 4; mt++)
        #pragma unroll
        for (int nt = 0; nt < 4; nt++) {
            int r = wm + mt * 16 + (lane >> 2);
            int c = wn + nt * 8 + (lane & 3) * 2;
            S[r * SROW + c]           = acc[mt][nt][0];
            S[r * SROW + c + 1]       = acc[mt][nt][1];
            S[(r + 8) * SROW + c]     = acc[mt][nt][2];
            S[(r + 8) * SROW + c + 1] = acc[mt][nt][3];
        }
    __syncthreads();
}

// ---------------- kernel: transpose + fp16 convert of x ------------------
__global__ void __launch_bounds__(128) k_conv(const float* __restrict__ x) {
    __shared__ float s[32][129];
    const int tid = threadIdx.x;
    const int n0 = blockIdx.x * 128;
    const int c0 = blockIdx.y * 32;
    const int b  = blockIdx.z;

    #pragma unroll
    for (int cc = 0; cc < 32; cc++)
        s[cc][tid] = x[((size_t)b * CIN + c0 + cc) * NPIX + n0 + tid];
    __syncthreads();

    uint32_t pk[16];
    #pragma unroll
    for (int cc = 0; cc < 32; cc += 2)
        pk[cc >> 1] = pack_h(__float2half(s[cc][tid]), __float2half(s[cc + 1][tid]));
    const size_t eb = ((size_t)b * NPIX + n0 + tid) * CIN + c0;
    uint4* d = (uint4*)&g_xt[eb];
    #pragma unroll
    for (int q = 0; q < 4; q++)
        d[q] = make_uint4(pk[q*4], pk[q*4+1], pk[q*4+2], pk[q*4+3]);
}

// ---------------- kernel: fp16 convert Wqkv + zero accumulators ----------
__global__ void k_wconv(const float* __restrict__ W) {
    int i = blockIdx.x * 256 + threadIdx.x;
    if (i < 384 * CIN) g_wq[i] = __float2half(W[i]);
    if (i < BATCH * HEADS * DH * DH) g_ctx[i] = 0.f;
    if (i < BATCH * 2) g_stats[i] = 0.f;
}

// ---------------- kernel: QKV GEMM + softmax epilogue --------------------
__global__ void __launch_bounds__(256, 2) k_qkv_mma(const float* __restrict__ bqkv)
{
    extern __shared__ char smem[];
    const uint32_t sbase = s2u(smem);
    float* S = (float*)smem;
    float* bias_s = (float*)(smem + BIAS_OFF);
    const int tid = threadIdx.x;
    const int n0 = blockIdx.x * 128;
    const int m  = blockIdx.y;
    const int b  = blockIdx.z;

    if (tid < 128) bias_s[tid] = bqkv[m * 128 + tid];

    float acc[4][4][4];
    #pragma unroll
    for (int i = 0; i < 4; i++)
        #pragma unroll
        for (int j = 0; j < 4; j++)
            #pragma unroll
            for (int q = 0; q < 4; q++) acc[i][j][q] = 0.f;

    gemm_block<CIN>(g_wq + m * 128 * CIN, CIN,
                    g_xt + ((size_t)b * NPIX + n0) * CIN, CIN,
                    sbase, acc);
    acc_to_smem(S, acc);

    const int col = tid & 127;
    const int half = tid >> 7;
    const int pixel = n0 + col;

    if (m == 2) {
        #pragma unroll 4
        for (int r = half * 64; r < half * 64 + 64; r++)
            g_v16[((size_t)b * HID + r) * NPIX + pixel] =
                __float2half(S[r * SROW + col] + bias_s[r]);
        return;
    }
    #pragma unroll
    for (int g = 0; g < 2; g++) {
        const int rb = half * 64 + g * 32;
        float v[32];
        float mx = -1e30f;
        #pragma unroll
        for (int j = 0; j < 32; j++) {
            v[j] = S[(rb + j) * SROW + col] + bias_s[rb + j];
            mx = fmaxf(mx, v[j]);
        }
        float s = 0.f;
        #pragma unroll
        for (int j = 0; j < 32; j++) { v[j] = __expf(v[j] - mx); s += v[j]; }
        float inv = 1.f / s;
        if (m == 0) inv *= QSCALE;
        if (m == 1) {
            #pragma unroll
            for (int j = 0; j < 32; j++)
                g_k16[((size_t)b * HID + rb + j) * NPIX + pixel] = __float2half(v[j] * inv);
        } else {
            uint32_t pk[16];
            #pragma unroll
            for (int j = 0; j < 32; j += 2)
                pk[j >> 1] = pack_h(__float2half(v[j] * inv), __float2half(v[j + 1] * inv));
            size_t e = ((size_t)b * NPIX + pixel) * HID + rb;
            uint4* d = (uint4*)&g_q[e];
            #pragma unroll
            for (int q = 0; q < 4; q++)
                d[q] = make_uint4(pk[q*4], pk[q*4+1], pk[q*4+2], pk[q*4+3]);
        }
    }
}

// ---------------- kernel: context[b,h,d,e] = sum_n k'[d,n] v[e,n] --------
// fp16 gmem -> fp32 smem staging; compute loop unchanged (R7-validated).
__global__ void __launch_bounds__(64) k_ctx()
{
    __shared__ float Ks[32][65];
    __shared__ float Vs[32][65];

    const int bh = blockIdx.x;
    const int seg = blockIdx.y;
    const int b = bh >> 2, h = bh & 3;
    const int tid = threadIdx.x;
    const int d0 = (tid >> 3) * 4;
    const int e0 = (tid & 7) * 4;

    float acc[4][4];
    #pragma unroll
    for (int i = 0; i < 4; i++)
        #pragma unroll
        for (int j = 0; j < 4; j++) acc[i][j] = 0.f;

    const __half* kp = g_k16 + ((size_t)b * HID + h * DH) * NPIX + seg * 256;
    const __half* vp = g_v16 + ((size_t)b * HID + h * DH) * NPIX + seg * 256;

    #pragma unroll 1
    for (int c0 = 0; c0 < 256; c0 += 64) {
        __syncthreads();
        #pragma unroll
        for (int i = 0; i < 32; i++) {
            Ks[i][tid] = __half2float(kp[(size_t)i * NPIX + c0 + tid]);
            Vs[i][tid] = __half2float(vp[(size_t)i * NPIX + c0 + tid]);
        }
        __syncthreads();
        #pragma unroll 4
        for (int nn = 0; nn < 64; nn++) {
            float ka[4], va[4];
            #pragma unroll
            for (int i = 0; i < 4; i++) ka[i] = Ks[d0 + i][nn];
            #pragma unroll
            for (int j = 0; j < 4; j++) va[j] = Vs[e0 + j][nn];
            #pragma unroll
            for (int i = 0; i < 4; i++)
                #pragma unroll
                for (int j = 0; j < 4; j++)
                    acc[i][j] += ka[i] * va[j];
        }
    }
    float* cdst = g_ctx + ((b * HEADS + h) * DH + d0) * DH + e0;
    #pragma unroll
    for (int i = 0; i < 4; i++)
        #pragma unroll
        for (int j = 0; j < 4; j++)
            atomicAdd(cdst + i * DH + j, acc[i][j]);
}

// ---------------- kernel: fold Wout with context -> fp16 -----------------
__global__ void __launch_bounds__(256) k_wp(const float* __restrict__ Wout)
{
    __shared__ float ctxs[HEADS * DH * 33];
    const int b = blockIdx.x;
    const int obase = blockIdx.y * 32;

    for (int i = threadIdx.x; i < HEADS * DH * DH; i += 256)
        ctxs[(i >> 5) * 33 + (i & 31)] = g_ctx[b * HEADS * DH * DH + i];
    __syncthreads();

    int hd = threadIdx.x & 127;
    int hb = hd & 0xE0;
    for (int oi = threadIdx.x >> 7; oi < 32; oi += 2) {
        int o = obase + oi;
        float s = 0.f;
        #pragma unroll
        for (int e = 0; e < 32; e++)
            s += Wout[o * HID + hb + e] * ctxs[hd * 33 + e];
        g_wp[((size_t)b * 256 + o) * HID + hd] = __float2half(s);
    }
}

// ---------------- kernel: projection GEMM + GN stats ---------------------
__global__ void __launch_bounds__(256, 2) k_proj_mma(
    const float* __restrict__ bout, float* __restrict__ out)
{
    extern __shared__ char smem[];
    const uint32_t sbase = s2u(smem);
    float* S = (float*)smem;
    float* bias_s = (float*)(smem + BIAS_OFF);
    const int tid = threadIdx.x;
    const int n0 = blockIdx.x * 128;
    const int o0 = blockIdx.y * 128;
    const int b  = blockIdx.z;

    if (tid < 128) bias_s[tid] = bout[o0 + tid];

    float acc[4][4][4];
    #pragma unroll
    for (int i = 0; i < 4; i++)
        #pragma unroll
        for (int j = 0; j < 4; j++)
            #pragma unroll
            for (int q = 0; q < 4; q++) acc[i][j][q] = 0.f;

    gemm_block<HID>(g_wp + ((size_t)b * 256 + o0) * HID, HID,
                    g_q + ((size_t)b * NPIX + n0) * HID, HID,
                    sbase, acc);
    acc_to_smem(S, acc);

    const int col = tid & 127;
    const int half = tid >> 7;
    const int pixel = n0 + col;
    float lsum = 0.f, lsq = 0.f;

    #pragma unroll 4
    for (int r = half * 64; r < half * 64 + 64; r++) {
        float val = S[r * SROW + col] + bias_s[r];
        lsum += val;
        lsq  += val * val;
        out[((size_t)b * 256 + o0 + r) * NPIX + pixel] = val;
    }
    #pragma unroll
    for (int off = 16; off > 0; off >>= 1) {
        lsum += __shfl_down_sync(0xffffffffu, lsum, off);
        lsq  += __shfl_down_sync(0xffffffffu, lsq,  off);
    }
    if ((tid & 31) == 0) {
        atomicAdd(&g_stats[b * 2 + 0], lsum);
        atomicAdd(&g_stats[b * 2 + 1], lsq);
    }
}

// ---------------- kernel: groupnorm normalize (in place) -----------------
__global__ void __launch_bounds__(256) k_norm(
    const float* __restrict__ gamma, const float* __restrict__ beta,
    float* __restrict__ out)
{
    size_t idx = ((size_t)blockIdx.x * 256 + threadIdx.x) * 4;
    int b = (int)(idx >> 20);
    int c = (int)((idx >> 12) & 255);
    float s1 = g_stats[b * 2 + 0];
    float s2 = g_stats[b * 2 + 1];
    float mu  = s1 * (1.f / NEL_F);
    float var = s2 * (1.f / NEL_F) - mu * mu;
    float rs = rsqrtf(var + GN_EPS);
    float gm = gamma[c] * rs;
    float bb = beta[c] - mu * gm;
    float4 v = *(const float4*)&out[idx];
    v.x = v.x * gm + bb;
    v.y = v.y * gm + bb;
    v.z = v.z * gm + bb;
    v.w = v.w * gm + bb;
    *(float4*)&out[idx] = v;
}

// ---------------- launch ----------------
extern "C" void kernel_launch(void* const* d_in, const int* in_sizes, int n_in,
                              void* d_out, int out_size)
{
    const float* x     = (const float*)d_in[0];
    const float* Wqkv  = (const float*)d_in[1];
    const float* bqkv  = (const float*)d_in[2];
    const float* Wout  = (const float*)d_in[3];
    const float* bout  = (const float*)d_in[4];
    const float* gamma = (const float*)d_in[5];
    const float* beta  = (const float*)d_in[6];
    float* out = (float*)d_out;

    static bool attr_done = false;
    if (!attr_done) {
        cudaFuncSetAttribute(k_qkv_mma,  cudaFuncAttributeMaxDynamicSharedMemorySize, SMEM_BYTES);
        cudaFuncSetAttribute(k_proj_mma, cudaFuncAttributeMaxDynamicSharedMemorySize, SMEM_BYTES);
        attr_done = true;
    }

    k_conv <<<dim3(32, 8, 32), 128>>>(x);
    k_wconv<<<512, 256>>>(Wqkv);
    k_qkv_mma <<<dim3(32, 3, 32), 256, SMEM_BYTES>>>(bqkv);
    k_ctx  <<<dim3(128, 16), 64>>>();
    k_wp   <<<dim3(32, 8), 256>>>(Wout);
    k_proj_mma<<<dim3(32, 2, 32), 256, SMEM_BYTES>>>(bout, out);
    k_norm <<<32768, 256>>>(gamma, beta, out);
}

// round 16
// speedup vs baseline: 1.6721x; 1.1034x over previous
#include <cuda_runtime.h>
#include <cuda_fp16.h>
#include <cstdint>

// ---------------- problem constants ----------------
#define BATCH   32
#define CIN     256
#define NPIX    4096
#define HID     128
#define HEADS   4
#define DH      32
#define QSCALE  0.17677669529663687f
#define GN_EPS  1e-5f
#define NEL_F   1048576.0f

// ---------------- scratch (device globals; no runtime alloc) -------------
__device__ __half g_xt [(size_t)BATCH * NPIX * CIN];   // x^T fp16 [b][n][c]
__device__ __half g_wq [384 * CIN];                    // Wqkv fp16 [o][c]
__device__ __half g_q  [(size_t)BATCH * NPIX * HID];   // q' fp16 [b][n][c]
__device__ __half g_k16[(size_t)BATCH * HID * NPIX];   // softmax(k) fp16 [b][c][n]
__device__ __half g_v16[(size_t)BATCH * HID * NPIX];   // v fp16 [b][c][n]
__device__ __half g_o16[(size_t)BATCH * 256 * NPIX];   // pre-GN out fp16
__device__ float g_ctx[BATCH * HEADS * DH * DH];
__device__ __half g_wp [BATCH * 256 * HID];            // W' fp16 [b][o][c]
__device__ float g_stats[BATCH * 2];

// ---------------- helpers ----------------
__device__ __forceinline__ uint32_t s2u(const void* p) {
    uint32_t a;
    asm("{ .reg .u64 t; cvta.to.shared.u64 t, %1; cvt.u32.u64 %0, t; }" : "=r"(a) : "l"(p));
    return a;
}
__device__ __forceinline__ uint32_t pack_h(__half a, __half b) {
    return (uint32_t)__half_as_ushort(a) | ((uint32_t)__half_as_ushort(b) << 16);
}

__device__ __forceinline__ void mma_f16(float d[4],
    uint32_t a0, uint32_t a1, uint32_t a2, uint32_t a3,
    uint32_t b0, uint32_t b1)
{
    asm("mma.sync.aligned.m16n8k16.row.col.f32.f16.f16.f32 "
        "{%0,%1,%2,%3}, {%4,%5,%6,%7}, {%8,%9}, {%0,%1,%2,%3};"
        : "+f"(d[0]), "+f"(d[1]), "+f"(d[2]), "+f"(d[3])
        : "r"(a0), "r"(a1), "r"(a2), "r"(a3), "r"(b0), "r"(b1));
}
__device__ __forceinline__ void ldsm4(uint32_t r[4], uint32_t addr) {
    asm volatile("ldmatrix.sync.aligned.m8n8.x4.shared.b16 {%0,%1,%2,%3}, [%4];"
        : "=r"(r[0]), "=r"(r[1]), "=r"(r[2]), "=r"(r[3]) : "r"(addr));
}
#define CPA(dst, src) asm volatile("cp.async.cg.shared.global [%0], [%1], 16;" :: "r"(dst), "l"(src))
#define CPC()  asm volatile("cp.async.commit_group;" ::: "memory")
#define CPW0() asm volatile("cp.async.wait_group 0;" ::: "memory")
#define CPW1() asm volatile("cp.async.wait_group 1;" ::: "memory")

// ---------------- GEMM core: plain fp16, fp32 accum ----------------------
#define ARR_B  (128 * 64)                   // 8192 bytes per array
#define STAGE1 (2 * ARR_B)                  // 16384 per stage
#define SROW 129
#define S_BYTES (128 * SROW * 4)            // 66048 (aliases stage area)
#define BIAS_OFF 66048
#define SMEM_BYTES (BIAS_OFF + 512)         // 66560

__device__ __forceinline__ uint32_t swadr(uint32_t sb, int arr, int row, int seg) {
    return sb + arr * ARR_B + row * 64 + (((uint32_t)(seg ^ ((row >> 1) & 3))) << 4);
}

__device__ __forceinline__ void stage_issue(
    uint32_t sb,
    const __half* __restrict__ A, int lda,
    const __half* __restrict__ B, int ldb,
    int kc)
{
    const int tid = threadIdx.x;
    const __half* gs[2] = {A, B};
    #pragma unroll
    for (int j = 0; j < 4; j++) {
        const int arr = j >> 1;
        const int ld  = (arr == 0) ? lda : ldb;
        const int idx = tid + (j & 1) * 256;     // 0..511
        const int r   = idx >> 2;
        const int s   = idx & 3;
        const __half* src = gs[arr] + (size_t)r * ld + kc + s * 8;
        CPA(swadr(sb, arr, r, s), src);
    }
    CPC();
}

__device__ __forceinline__ void chunk_compute(uint32_t sb, float acc[4][4][4]) {
    const int lane = threadIdx.x & 31;
    const int wid  = threadIdx.x >> 5;
    const int wm   = (wid >> 2) * 64;
    const int wn   = (wid & 3) * 32;
    const int ra   = lane & 15;
    const int sa   = lane >> 4;
    const int rb   = ((lane >> 4) & 1) * 8 + (lane & 7);
    const int sbg  = (lane >> 3) & 1;

    uint32_t aad[4], bad[2];
    #pragma unroll
    for (int mt = 0; mt < 4; mt++)
        aad[mt] = swadr(sb, 0, wm + mt * 16 + ra, sa);
    #pragma unroll
    for (int pr = 0; pr < 2; pr++)
        bad[pr] = swadr(sb, 1, wn + pr * 16 + rb, sbg);

    #pragma unroll
    for (int ks = 0; ks < 2; ks++) {
        const uint32_t xr = ks ? 0x20u : 0u;
        uint32_t ah[4][4], bh[2][4];
        #pragma unroll
        for (int mt = 0; mt < 4; mt++)
            ldsm4(ah[mt], aad[mt] ^ xr);
        #pragma unroll
        for (int pr = 0; pr < 2; pr++)
            ldsm4(bh[pr], bad[pr] ^ xr);
        #pragma unroll
        for (int mt = 0; mt < 4; mt++)
            #pragma unroll
            for (int nt = 0; nt < 4; nt++) {
                uint32_t b0 = bh[nt >> 1][(nt & 1) * 2], b1 = bh[nt >> 1][(nt & 1) * 2 + 1];
                mma_f16(acc[mt][nt], ah[mt][0], ah[mt][1], ah[mt][2], ah[mt][3], b0, b1);
            }
    }
}

template<int KTOT>
__device__ __forceinline__ void gemm_block(
    const __half* __restrict__ A, int lda,
    const __half* __restrict__ B, int ldb,
    uint32_t sbase, float acc[4][4][4])
{
    constexpr int NCHUNK = KTOT / 32;
    stage_issue(sbase, A, lda, B, ldb, 0);
    if (NCHUNK > 1) stage_issue(sbase + STAGE1, A, lda, B, ldb, 32);
    #pragma unroll 1
    for (int c = 0; c < NCHUNK; c++) {
        if (c + 1 < NCHUNK) { CPW1(); } else { CPW0(); }
        __syncthreads();
        if (c + 2 < NCHUNK) {
            const uint32_t nbuf = sbase + ((c + 2) % 3) * STAGE1;
            stage_issue(nbuf, A, lda, B, ldb, (c + 2) * 32);
        }
        chunk_compute(sbase + (c % 3) * STAGE1, acc);
    }
    __syncthreads();
}

__device__ __forceinline__ void acc_to_smem(float* S, float acc[4][4][4]) {
    const int lane = threadIdx.x & 31;
    const int wid  = threadIdx.x >> 5;
    const int wm   = (wid >> 2) * 64;
    const int wn   = (wid & 3) * 32;
    #pragma unroll
    for (int mt = 0; mt < 4; mt++)
        #pragma unroll
        for (int nt = 0; nt < 4; nt++) {
            int r = wm + mt * 16 + (lane >> 2);
            int c = wn + nt * 8 + (lane & 3) * 2;
            S[r * SROW + c]           = acc[mt][nt][0];
            S[r * SROW + c + 1]       = acc[mt][nt][1];
            S[(r + 8) * SROW + c]     = acc[mt][nt][2];
            S[(r + 8) * SROW + c + 1] = acc[mt][nt][3];
        }
    __syncthreads();
}

// ---------------- kernel: transpose + fp16 convert of x ------------------
__global__ void __launch_bounds__(128) k_conv(const float* __restrict__ x) {
    __shared__ float s[32][129];
    const int tid = threadIdx.x;
    const int n0 = blockIdx.x * 128;
    const int c0 = blockIdx.y * 32;
    const int b  = blockIdx.z;

    #pragma unroll
    for (int cc = 0; cc < 32; cc++)
        s[cc][tid] = x[((size_t)b * CIN + c0 + cc) * NPIX + n0 + tid];
    __syncthreads();

    uint32_t pk[16];
    #pragma unroll
    for (int cc = 0; cc < 32; cc += 2)
        pk[cc >> 1] = pack_h(__float2half(s[cc][tid]), __float2half(s[cc + 1][tid]));
    const size_t eb = ((size_t)b * NPIX + n0 + tid) * CIN + c0;
    uint4* d = (uint4*)&g_xt[eb];
    #pragma unroll
    for (int q = 0; q < 4; q++)
        d[q] = make_uint4(pk[q*4], pk[q*4+1], pk[q*4+2], pk[q*4+3]);
}

// ---------------- kernel: fp16 convert Wqkv + zero accumulators ----------
__global__ void k_wconv(const float* __restrict__ W) {
    int i = blockIdx.x * 256 + threadIdx.x;
    if (i < 384 * CIN) g_wq[i] = __float2half(W[i]);
    if (i < BATCH * HEADS * DH * DH) g_ctx[i] = 0.f;
    if (i < BATCH * 2) g_stats[i] = 0.f;
}

// ---------------- kernel: QKV GEMM + softmax epilogue --------------------
__global__ void __launch_bounds__(256, 2) k_qkv_mma(const float* __restrict__ bqkv)
{
    extern __shared__ char smem[];
    const uint32_t sbase = s2u(smem);
    float* S = (float*)smem;
    float* bias_s = (float*)(smem + BIAS_OFF);
    const int tid = threadIdx.x;
    const int n0 = blockIdx.x * 128;
    const int m  = blockIdx.y;
    const int b  = blockIdx.z;

    if (tid < 128) bias_s[tid] = bqkv[m * 128 + tid];

    float acc[4][4][4];
    #pragma unroll
    for (int i = 0; i < 4; i++)
        #pragma unroll
        for (int j = 0; j < 4; j++)
            #pragma unroll
            for (int q = 0; q < 4; q++) acc[i][j][q] = 0.f;

    gemm_block<CIN>(g_wq + m * 128 * CIN, CIN,
                    g_xt + ((size_t)b * NPIX + n0) * CIN, CIN,
                    sbase, acc);
    acc_to_smem(S, acc);

    const int col = tid & 127;
    const int half = tid >> 7;
    const int pixel = n0 + col;

    if (m == 2) {
        #pragma unroll 4
        for (int r = half * 64; r < half * 64 + 64; r++)
            g_v16[((size_t)b * HID + r) * NPIX + pixel] =
                __float2half(S[r * SROW + col] + bias_s[r]);
        return;
    }
    #pragma unroll
    for (int g = 0; g < 2; g++) {
        const int rb = half * 64 + g * 32;
        float v[32];
        float mx = -1e30f;
        #pragma unroll
        for (int j = 0; j < 32; j++) {
            v[j] = S[(rb + j) * SROW + col] + bias_s[rb + j];
            mx = fmaxf(mx, v[j]);
        }
        float s = 0.f;
        #pragma unroll
        for (int j = 0; j < 32; j++) { v[j] = __expf(v[j] - mx); s += v[j]; }
        float inv = 1.f / s;
        if (m == 0) inv *= QSCALE;
        if (m == 1) {
            #pragma unroll
            for (int j = 0; j < 32; j++)
                g_k16[((size_t)b * HID + rb + j) * NPIX + pixel] = __float2half(v[j] * inv);
        } else {
            uint32_t pk[16];
            #pragma unroll
            for (int j = 0; j < 32; j += 2)
                pk[j >> 1] = pack_h(__float2half(v[j] * inv), __float2half(v[j + 1] * inv));
            size_t e = ((size_t)b * NPIX + pixel) * HID + rb;
            uint4* d = (uint4*)&g_q[e];
            #pragma unroll
            for (int q = 0; q < 4; q++)
                d[q] = make_uint4(pk[q*4], pk[q*4+1], pk[q*4+2], pk[q*4+3]);
        }
    }
}

// ---------------- kernel: context via HMMA --------------------------------
// ctx[b,h] (32x32) = k[32 x 4096] . v[32 x 4096]^T ; both fp16 n-contiguous.
// Fragments loaded straight from gmem (no smem/ldmatrix). grid (128 bh, 8 seg),
// 128 threads = 4 warps, each warp covers 128 n. fp32 accum, atomic reduce.
__global__ void __launch_bounds__(128) k_ctx()
{
    const int bh = blockIdx.x;
    const int b = bh >> 2, h = bh & 3;
    const int w = threadIdx.x >> 5;
    const int lane = threadIdx.x & 31;
    const int n_base = blockIdx.y * 512 + w * 128;

    const __half* kp = g_k16 + ((size_t)b * HID + h * DH) * NPIX;
    const __half* vp = g_v16 + ((size_t)b * HID + h * DH) * NPIX;

    const int lr = lane >> 2;          // 0..7
    const int lc = (lane & 3) * 2;     // 0,2,4,6

    float acc[2][4][4];
    #pragma unroll
    for (int i = 0; i < 2; i++)
        #pragma unroll
        for (int j = 0; j < 4; j++)
            #pragma unroll
            for (int q = 0; q < 4; q++) acc[i][j][q] = 0.f;

    #pragma unroll 2
    for (int ns = 0; ns < 128; ns += 16) {
        const int n0 = n_base + ns;
        uint32_t a[2][4];
        #pragma unroll
        for (int mt = 0; mt < 2; mt++) {
            const __half* ab = kp + (size_t)(mt * 16 + lr) * NPIX + n0 + lc;
            a[mt][0] = *(const uint32_t*)ab;
            a[mt][1] = *(const uint32_t*)(ab + 8 * NPIX);
            a[mt][2] = *(const uint32_t*)(ab + 8);
            a[mt][3] = *(const uint32_t*)(ab + 8 * NPIX + 8);
        }
        uint32_t bf[4][2];
        #pragma unroll
        for (int nt = 0; nt < 4; nt++) {
            const __half* vb = vp + (size_t)(nt * 8 + lr) * NPIX + n0 + lc;
            bf[nt][0] = *(const uint32_t*)vb;
            bf[nt][1] = *(const uint32_t*)(vb + 8);
        }
        #pragma unroll
        for (int mt = 0; mt < 2; mt++)
            #pragma unroll
            for (int nt = 0; nt < 4; nt++)
                mma_f16(acc[mt][nt], a[mt][0], a[mt][1], a[mt][2], a[mt][3],
                        bf[nt][0], bf[nt][1]);
    }

    float* cbase = g_ctx + (b * HEADS + h) * DH * DH;
    #pragma unroll
    for (int mt = 0; mt < 2; mt++)
        #pragma unroll
        for (int nt = 0; nt < 4; nt++) {
            int d = mt * 16 + lr, e = nt * 8 + lc;
            atomicAdd(&cbase[d * DH + e],           acc[mt][nt][0]);
            atomicAdd(&cbase[d * DH + e + 1],       acc[mt][nt][1]);
            atomicAdd(&cbase[(d + 8) * DH + e],     acc[mt][nt][2]);
            atomicAdd(&cbase[(d + 8) * DH + e + 1], acc[mt][nt][3]);
        }
}

// ---------------- kernel: fold Wout with context -> fp16 -----------------
__global__ void __launch_bounds__(256) k_wp(const float* __restrict__ Wout)
{
    __shared__ float ctxs[HEADS * DH * 33];
    const int b = blockIdx.x;
    const int obase = blockIdx.y * 32;

    for (int i = threadIdx.x; i < HEADS * DH * DH; i += 256)
        ctxs[(i >> 5) * 33 + (i & 31)] = g_ctx[b * HEADS * DH * DH + i];
    __syncthreads();

    int hd = threadIdx.x & 127;
    int hb = hd & 0xE0;
    for (int oi = threadIdx.x >> 7; oi < 32; oi += 2) {
        int o = obase + oi;
        float s = 0.f;
        #pragma unroll
        for (int e = 0; e < 32; e++)
            s += Wout[o * HID + hb + e] * ctxs[hd * 33 + e];
        g_wp[((size_t)b * 256 + o) * HID + hd] = __float2half(s);
    }
}

// ---------------- kernel: projection GEMM + GN stats (fp16 out) ----------
__global__ void __launch_bounds__(256, 2) k_proj_mma(const float* __restrict__ bout)
{
    extern __shared__ char smem[];
    const uint32_t sbase = s2u(smem);
    float* S = (float*)smem;
    float* bias_s = (float*)(smem + BIAS_OFF);
    const int tid = threadIdx.x;
    const int n0 = blockIdx.x * 128;
    const int o0 = blockIdx.y * 128;
    const int b  = blockIdx.z;

    if (tid < 128) bias_s[tid] = bout[o0 + tid];

    float acc[4][4][4];
    #pragma unroll
    for (int i = 0; i < 4; i++)
        #pragma unroll
        for (int j = 0; j < 4; j++)
            #pragma unroll
            for (int q = 0; q < 4; q++) acc[i][j][q] = 0.f;

    gemm_block<HID>(g_wp + ((size_t)b * 256 + o0) * HID, HID,
                    g_q + ((size_t)b * NPIX + n0) * HID, HID,
                    sbase, acc);
    acc_to_smem(S, acc);

    const int col = tid & 127;
    const int half = tid >> 7;
    const int pixel = n0 + col;
    float lsum = 0.f, lsq = 0.f;

    #pragma unroll 4
    for (int r = half * 64; r < half * 64 + 64; r++) {
        float val = S[r * SROW + col] + bias_s[r];
        lsum += val;
        lsq  += val * val;
        g_o16[((size_t)b * 256 + o0 + r) * NPIX + pixel] = __float2half(val);
    }
    #pragma unroll
    for (int off = 16; off > 0; off >>= 1) {
        lsum += __shfl_down_sync(0xffffffffu, lsum, off);
        lsq  += __shfl_down_sync(0xffffffffu, lsq,  off);
    }
    if ((tid & 31) == 0) {
        atomicAdd(&g_stats[b * 2 + 0], lsum);
        atomicAdd(&g_stats[b * 2 + 1], lsq);
    }
}

// ---------------- kernel: groupnorm normalize (fp16 in, fp32 out) --------
__global__ void __launch_bounds__(256) k_norm(
    const float* __restrict__ gamma, const float* __restrict__ beta,
    float* __restrict__ out)
{
    size_t idx = ((size_t)blockIdx.x * 256 + threadIdx.x) * 4;
    int b = (int)(idx >> 20);
    int c = (int)((idx >> 12) & 255);
    float s1 = g_stats[b * 2 + 0];
    float s2 = g_stats[b * 2 + 1];
    float mu  = s1 * (1.f / NEL_F);
    float var = s2 * (1.f / NEL_F) - mu * mu;
    float rs = rsqrtf(var + GN_EPS);
    float gm = gamma[c] * rs;
    float bb = beta[c] - mu * gm;
    uint2 pk = *(const uint2*)&g_o16[idx];
    __half2 h0 = *(__half2*)&pk.x;
    __half2 h1 = *(__half2*)&pk.y;
    float4 v;
    v.x = __low2float(h0)  * gm + bb;
    v.y = __high2float(h0) * gm + bb;
    v.z = __low2float(h1)  * gm + bb;
    v.w = __high2float(h1) * gm + bb;
    *(float4*)&out[idx] = v;
}

// ---------------- launch ----------------
extern "C" void kernel_launch(void* const* d_in, const int* in_sizes, int n_in,
                              void* d_out, int out_size)
{
    const float* x     = (const float*)d_in[0];
    const float* Wqkv  = (const float*)d_in[1];
    const float* bqkv  = (const float*)d_in[2];
    const float* Wout  = (const float*)d_in[3];
    const float* bout  = (const float*)d_in[4];
    const float* gamma = (const float*)d_in[5];
    const float* beta  = (const float*)d_in[6];
    float* out = (float*)d_out;

    static bool attr_done = false;
    if (!attr_done) {
        cudaFuncSetAttribute(k_qkv_mma,  cudaFuncAttributeMaxDynamicSharedMemorySize, SMEM_BYTES);
        cudaFuncSetAttribute(k_proj_mma, cudaFuncAttributeMaxDynamicSharedMemorySize, SMEM_BYTES);
        attr_done = true;
    }

    k_conv <<<dim3(32, 8, 32), 128>>>(x);
    k_wconv<<<512, 256>>>(Wqkv);
    k_qkv_mma <<<dim3(32, 3, 32), 256, SMEM_BYTES>>>(bqkv);
    k_ctx  <<<dim3(128, 8), 128>>>();
    k_wp   <<<dim3(32, 8), 256>>>(Wout);
    k_proj_mma<<<dim3(32, 2, 32), 256, SMEM_BYTES>>>(bout);
    k_norm <<<32768, 256>>>(gamma, beta, out);
}

// round 17
// speedup vs baseline: 1.7061x; 1.0204x over previous
#include <cuda_runtime.h>
#include <cuda_fp16.h>
#include <cstdint>

// ---------------- problem constants ----------------
#define BATCH   32
#define CIN     256
#define NPIX    4096
#define HID     128
#define HEADS   4
#define DH      32
#define QSCALE  0.17677669529663687f
#define GN_EPS  1e-5f
#define NEL_F   1048576.0f

// ---------------- scratch (device globals; no runtime alloc) -------------
__device__ __half g_xt [(size_t)BATCH * NPIX * CIN];   // x^T fp16 [b][n][c]
__device__ __half g_wq [384 * CIN];                    // Wqkv fp16 [o][c]
__device__ __half g_q  [(size_t)BATCH * NPIX * HID];   // q' fp16 [b][n][c]
__device__ __half g_k16[(size_t)BATCH * HID * NPIX];   // softmax(k) fp16 [b][c][n]
__device__ __half g_v16[(size_t)BATCH * HID * NPIX];   // v fp16 [b][c][n]
__device__ __half g_o16[(size_t)BATCH * 256 * NPIX];   // pre-GN out fp16
__device__ float g_ctx[BATCH * HEADS * DH * DH];
__device__ __half g_wp [BATCH * 256 * HID];            // W' fp16 [b][o][c]
__device__ float g_stats[BATCH * 2];

// ---------------- helpers ----------------
__device__ __forceinline__ uint32_t s2u(const void* p) {
    uint32_t a;
    asm("{ .reg .u64 t; cvta.to.shared.u64 t, %1; cvt.u32.u64 %0, t; }" : "=r"(a) : "l"(p));
    return a;
}
__device__ __forceinline__ uint32_t pack_h(__half a, __half b) {
    return (uint32_t)__half_as_ushort(a) | ((uint32_t)__half_as_ushort(b) << 16);
}

__device__ __forceinline__ void mma_f16(float d[4],
    uint32_t a0, uint32_t a1, uint32_t a2, uint32_t a3,
    uint32_t b0, uint32_t b1)
{
    asm("mma.sync.aligned.m16n8k16.row.col.f32.f16.f16.f32 "
        "{%0,%1,%2,%3}, {%4,%5,%6,%7}, {%8,%9}, {%0,%1,%2,%3};"
        : "+f"(d[0]), "+f"(d[1]), "+f"(d[2]), "+f"(d[3])
        : "r"(a0), "r"(a1), "r"(a2), "r"(a3), "r"(b0), "r"(b1));
}
__device__ __forceinline__ void ldsm4(uint32_t r[4], uint32_t addr) {
    asm volatile("ldmatrix.sync.aligned.m8n8.x4.shared.b16 {%0,%1,%2,%3}, [%4];"
        : "=r"(r[0]), "=r"(r[1]), "=r"(r[2]), "=r"(r[3]) : "r"(addr));
}
#define CPA(dst, src) asm volatile("cp.async.cg.shared.global [%0], [%1], 16;" :: "r"(dst), "l"(src))
#define CPC()  asm volatile("cp.async.commit_group;" ::: "memory")
#define CPW0() asm volatile("cp.async.wait_group 0;" ::: "memory")
#define CPW1() asm volatile("cp.async.wait_group 1;" ::: "memory")

// ---------------- GEMM core: plain fp16, fp32 accum ----------------------
#define ARR_B  (128 * 64)                   // 8192 bytes per array
#define STAGE1 (2 * ARR_B)                  // 16384 per stage
#define SROW 129
#define S_BYTES (128 * SROW * 4)            // 66048 (aliases stage area)
#define BIAS_OFF 66048
#define SMEM_BYTES (BIAS_OFF + 512)         // 66560

__device__ __forceinline__ uint32_t swadr(uint32_t sb, int arr, int row, int seg) {
    return sb + arr * ARR_B + row * 64 + (((uint32_t)(seg ^ ((row >> 1) & 3))) << 4);
}
// same swizzle, arbitrary base (used by k_ctx 32-row arrays)
__device__ __forceinline__ uint32_t cswadr(uint32_t base, int row, int seg) {
    return base + row * 64 + (((uint32_t)(seg ^ ((row >> 1) & 3))) << 4);
}

__device__ __forceinline__ void stage_issue(
    uint32_t sb,
    const __half* __restrict__ A, int lda,
    const __half* __restrict__ B, int ldb,
    int kc)
{
    const int tid = threadIdx.x;
    const __half* gs[2] = {A, B};
    #pragma unroll
    for (int j = 0; j < 4; j++) {
        const int arr = j >> 1;
        const int ld  = (arr == 0) ? lda : ldb;
        const int idx = tid + (j & 1) * 256;     // 0..511
        const int r   = idx >> 2;
        const int s   = idx & 3;
        const __half* src = gs[arr] + (size_t)r * ld + kc + s * 8;
        CPA(swadr(sb, arr, r, s), src);
    }
    CPC();
}

__device__ __forceinline__ void chunk_compute(uint32_t sb, float acc[4][4][4]) {
    const int lane = threadIdx.x & 31;
    const int wid  = threadIdx.x >> 5;
    const int wm   = (wid >> 2) * 64;
    const int wn   = (wid & 3) * 32;
    const int ra   = lane & 15;
    const int sa   = lane >> 4;
    const int rb   = ((lane >> 4) & 1) * 8 + (lane & 7);
    const int sbg  = (lane >> 3) & 1;

    uint32_t aad[4], bad[2];
    #pragma unroll
    for (int mt = 0; mt < 4; mt++)
        aad[mt] = swadr(sb, 0, wm + mt * 16 + ra, sa);
    #pragma unroll
    for (int pr = 0; pr < 2; pr++)
        bad[pr] = swadr(sb, 1, wn + pr * 16 + rb, sbg);

    #pragma unroll
    for (int ks = 0; ks < 2; ks++) {
        const uint32_t xr = ks ? 0x20u : 0u;
        uint32_t ah[4][4], bh[2][4];
        #pragma unroll
        for (int mt = 0; mt < 4; mt++)
            ldsm4(ah[mt], aad[mt] ^ xr);
        #pragma unroll
        for (int pr = 0; pr < 2; pr++)
            ldsm4(bh[pr], bad[pr] ^ xr);
        #pragma unroll
        for (int mt = 0; mt < 4; mt++)
            #pragma unroll
            for (int nt = 0; nt < 4; nt++) {
                uint32_t b0 = bh[nt >> 1][(nt & 1) * 2], b1 = bh[nt >> 1][(nt & 1) * 2 + 1];
                mma_f16(acc[mt][nt], ah[mt][0], ah[mt][1], ah[mt][2], ah[mt][3], b0, b1);
            }
    }
}

template<int KTOT>
__device__ __forceinline__ void gemm_block(
    const __half* __restrict__ A, int lda,
    const __half* __restrict__ B, int ldb,
    uint32_t sbase, float acc[4][4][4])
{
    constexpr int NCHUNK = KTOT / 32;
    stage_issue(sbase, A, lda, B, ldb, 0);
    if (NCHUNK > 1) stage_issue(sbase + STAGE1, A, lda, B, ldb, 32);
    #pragma unroll 1
    for (int c = 0; c < NCHUNK; c++) {
        if (c + 1 < NCHUNK) { CPW1(); } else { CPW0(); }
        __syncthreads();
        if (c + 2 < NCHUNK) {
            const uint32_t nbuf = sbase + ((c + 2) % 3) * STAGE1;
            stage_issue(nbuf, A, lda, B, ldb, (c + 2) * 32);
        }
        chunk_compute(sbase + (c % 3) * STAGE1, acc);
    }
    __syncthreads();
}

__device__ __forceinline__ void acc_to_smem(float* S, float acc[4][4][4]) {
    const int lane = threadIdx.x & 31;
    const int wid  = threadIdx.x >> 5;
    const int wm   = (wid >> 2) * 64;
    const int wn   = (wid & 3) * 32;
    #pragma unroll
    for (int mt = 0; mt < 4; mt++)
        #pragma unroll
        for (int nt = 0; nt < 4; nt++) {
            int r = wm + mt * 16 + (lane >> 2);
            int c = wn + nt * 8 + (lane & 3) * 2;
            S[r * SROW + c]           = acc[mt][nt][0];
            S[r * SROW + c + 1]       = acc[mt][nt][1];
            S[(r + 8) * SROW + c]     = acc[mt][nt][2];
            S[(r + 8) * SROW + c + 1] = acc[mt][nt][3];
        }
    __syncthreads();
}

// ---------------- kernel: transpose + fp16 convert of x ------------------
__global__ void __launch_bounds__(128) k_conv(const float* __restrict__ x) {
    __shared__ float s[32][129];
    const int tid = threadIdx.x;
    const int n0 = blockIdx.x * 128;
    const int c0 = blockIdx.y * 32;
    const int b  = blockIdx.z;

    #pragma unroll
    for (int cc = 0; cc < 32; cc++)
        s[cc][tid] = x[((size_t)b * CIN + c0 + cc) * NPIX + n0 + tid];
    __syncthreads();

    uint32_t pk[16];
    #pragma unroll
    for (int cc = 0; cc < 32; cc += 2)
        pk[cc >> 1] = pack_h(__float2half(s[cc][tid]), __float2half(s[cc + 1][tid]));
    const size_t eb = ((size_t)b * NPIX + n0 + tid) * CIN + c0;
    uint4* d = (uint4*)&g_xt[eb];
    #pragma unroll
    for (int q = 0; q < 4; q++)
        d[q] = make_uint4(pk[q*4], pk[q*4+1], pk[q*4+2], pk[q*4+3]);
}

// ---------------- kernel: fp16 convert Wqkv + zero accumulators ----------
__global__ void k_wconv(const float* __restrict__ W) {
    int i = blockIdx.x * 256 + threadIdx.x;
    if (i < 384 * CIN) g_wq[i] = __float2half(W[i]);
    if (i < BATCH * HEADS * DH * DH) g_ctx[i] = 0.f;
    if (i < BATCH * 2) g_stats[i] = 0.f;
}

// ---------------- kernel: QKV GEMM + softmax epilogue --------------------
__global__ void __launch_bounds__(256, 2) k_qkv_mma(const float* __restrict__ bqkv)
{
    extern __shared__ char smem[];
    const uint32_t sbase = s2u(smem);
    float* S = (float*)smem;
    float* bias_s = (float*)(smem + BIAS_OFF);
    const int tid = threadIdx.x;
    const int n0 = blockIdx.x * 128;
    const int m  = blockIdx.y;
    const int b  = blockIdx.z;

    if (tid < 128) bias_s[tid] = bqkv[m * 128 + tid];

    float acc[4][4][4];
    #pragma unroll
    for (int i = 0; i < 4; i++)
        #pragma unroll
        for (int j = 0; j < 4; j++)
            #pragma unroll
            for (int q = 0; q < 4; q++) acc[i][j][q] = 0.f;

    gemm_block<CIN>(g_wq + m * 128 * CIN, CIN,
                    g_xt + ((size_t)b * NPIX + n0) * CIN, CIN,
                    sbase, acc);
    acc_to_smem(S, acc);

    const int col = tid & 127;
    const int half = tid >> 7;
    const int pixel = n0 + col;

    if (m == 2) {
        #pragma unroll 4
        for (int r = half * 64; r < half * 64 + 64; r++)
            g_v16[((size_t)b * HID + r) * NPIX + pixel] =
                __float2half(S[r * SROW + col] + bias_s[r]);
        return;
    }
    #pragma unroll
    for (int g = 0; g < 2; g++) {
        const int rb = half * 64 + g * 32;
        float v[32];
        float mx = -1e30f;
        #pragma unroll
        for (int j = 0; j < 32; j++) {
            v[j] = S[(rb + j) * SROW + col] + bias_s[rb + j];
            mx = fmaxf(mx, v[j]);
        }
        float s = 0.f;
        #pragma unroll
        for (int j = 0; j < 32; j++) { v[j] = __expf(v[j] - mx); s += v[j]; }
        float inv = 1.f / s;
        if (m == 0) inv *= QSCALE;
        if (m == 1) {
            #pragma unroll
            for (int j = 0; j < 32; j++)
                g_k16[((size_t)b * HID + rb + j) * NPIX + pixel] = __float2half(v[j] * inv);
        } else {
            uint32_t pk[16];
            #pragma unroll
            for (int j = 0; j < 32; j += 2)
                pk[j >> 1] = pack_h(__float2half(v[j] * inv), __float2half(v[j + 1] * inv));
            size_t e = ((size_t)b * NPIX + pixel) * HID + rb;
            uint4* d = (uint4*)&g_q[e];
            #pragma unroll
            for (int q = 0; q < 4; q++)
                d[q] = make_uint4(pk[q*4], pk[q*4+1], pk[q*4+2], pk[q*4+3]);
        }
    }
}

// ---------------- kernel: context via HMMA + cp.async/ldmatrix -----------
// ctx[b,h] (32x32) = k[32 x 4096] . v[32 x 4096]^T; fp16 n-contiguous.
// Groups of 128 n = 4 chunks of 32 n (one chunk per warp). K/V arrays are
// 32 rows x 64 B, same swizzle as the GEMM core. 3 buffers, 2 in flight.
#define CARR 2048                 // 32 rows * 64 B
#define CCH  (2 * CARR)           // K + V per chunk
#define CGRP (4 * CCH)            // 4 chunks = 16384
__global__ void __launch_bounds__(128) k_ctx()
{
    __shared__ char csm[3 * CGRP];          // 48 KB
    const uint32_t cbase = s2u(csm);
    const int bh = blockIdx.x;
    const int b = bh >> 2, h = bh & 3;
    const int tid = threadIdx.x;
    const int w = tid >> 5;
    const int lane = tid & 31;

    const __half* kp = g_k16 + ((size_t)b * HID + h * DH) * NPIX + blockIdx.y * 512;
    const __half* vp = g_v16 + ((size_t)b * HID + h * DH) * NPIX + blockIdx.y * 512;

    // stage group g (128 n) into buffer at sb: 8 x 16B cp.async per thread
    auto stage = [&](uint32_t sb, int g) {
        const int r = tid >> 2, s = tid & 3;      // r 0..31, s 0..3
        #pragma unroll
        for (int ch = 0; ch < 4; ch++) {
            const int noff = g * 128 + ch * 32 + s * 8;
            CPA(cswadr(sb + ch * CCH,        r, s), kp + (size_t)r * NPIX + noff);
            CPA(cswadr(sb + ch * CCH + CARR, r, s), vp + (size_t)r * NPIX + noff);
        }
        CPC();
    };

    float acc[2][4][4];
    #pragma unroll
    for (int i = 0; i < 2; i++)
        #pragma unroll
        for (int j = 0; j < 4; j++)
            #pragma unroll
            for (int q = 0; q < 4; q++) acc[i][j][q] = 0.f;

    const int ra  = lane & 15;
    const int sa  = lane >> 4;
    const int rb  = ((lane >> 4) & 1) * 8 + (lane & 7);
    const int sbg = (lane >> 3) & 1;

    stage(cbase, 0);
    stage(cbase + CGRP, 1);
    #pragma unroll 1
    for (int it = 0; it < 4; it++) {
        if (it + 1 < 4) { CPW1(); } else { CPW0(); }
        __syncthreads();
        if (it + 2 < 4)
            stage(cbase + ((it + 2) % 3) * CGRP, it + 2);
        const uint32_t cb = cbase + (it % 3) * CGRP + w * CCH;
        uint32_t aad[2], bad[2];
        #pragma unroll
        for (int mt = 0; mt < 2; mt++) aad[mt] = cswadr(cb, mt * 16 + ra, sa);
        #pragma unroll
        for (int pr = 0; pr < 2; pr++) bad[pr] = cswadr(cb + CARR, pr * 16 + rb, sbg);
        #pragma unroll
        for (int ks = 0; ks < 2; ks++) {
            const uint32_t xr = ks ? 0x20u : 0u;
            uint32_t a[2][4], bv[2][4];
            #pragma unroll
            for (int mt = 0; mt < 2; mt++) ldsm4(a[mt], aad[mt] ^ xr);
            #pragma unroll
            for (int pr = 0; pr < 2; pr++) ldsm4(bv[pr], bad[pr] ^ xr);
            #pragma unroll
            for (int mt = 0; mt < 2; mt++)
                #pragma unroll
                for (int nt = 0; nt < 4; nt++) {
                    uint32_t b0 = bv[nt >> 1][(nt & 1) * 2], b1 = bv[nt >> 1][(nt & 1) * 2 + 1];
                    mma_f16(acc[mt][nt], a[mt][0], a[mt][1], a[mt][2], a[mt][3], b0, b1);
                }
        }
    }

    float* cb2 = g_ctx + (b * HEADS + h) * DH * DH;
    const int lr = lane >> 2;
    const int lc = (lane & 3) * 2;
    #pragma unroll
    for (int mt = 0; mt < 2; mt++)
        #pragma unroll
        for (int nt = 0; nt < 4; nt++) {
            int d = mt * 16 + lr, e = nt * 8 + lc;
            atomicAdd(&cb2[d * DH + e],           acc[mt][nt][0]);
            atomicAdd(&cb2[d * DH + e + 1],       acc[mt][nt][1]);
            atomicAdd(&cb2[(d + 8) * DH + e],     acc[mt][nt][2]);
            atomicAdd(&cb2[(d + 8) * DH + e + 1], acc[mt][nt][3]);
        }
}

// ---------------- kernel: fold Wout with context -> fp16 -----------------
__global__ void __launch_bounds__(256) k_wp(const float* __restrict__ Wout)
{
    __shared__ float ctxs[HEADS * DH * 33];
    const int b = blockIdx.x;
    const int obase = blockIdx.y * 32;

    for (int i = threadIdx.x; i < HEADS * DH * DH; i += 256)
        ctxs[(i >> 5) * 33 + (i & 31)] = g_ctx[b * HEADS * DH * DH + i];
    __syncthreads();

    int hd = threadIdx.x & 127;
    int hb = hd & 0xE0;
    for (int oi = threadIdx.x >> 7; oi < 32; oi += 2) {
        int o = obase + oi;
        float s = 0.f;
        #pragma unroll
        for (int e = 0; e < 32; e++)
            s += Wout[o * HID + hb + e] * ctxs[hd * 33 + e];
        g_wp[((size_t)b * 256 + o) * HID + hd] = __float2half(s);
    }
}

// ---------------- kernel: projection GEMM + GN stats (fp16 out) ----------
__global__ void __launch_bounds__(256, 2) k_proj_mma(const float* __restrict__ bout)
{
    extern __shared__ char smem[];
    const uint32_t sbase = s2u(smem);
    float* S = (float*)smem;
    float* bias_s = (float*)(smem + BIAS_OFF);
    const int tid = threadIdx.x;
    const int n0 = blockIdx.x * 128;
    const int o0 = blockIdx.y * 128;
    const int b  = blockIdx.z;

    if (tid < 128) bias_s[tid] = bout[o0 + tid];

    float acc[4][4][4];
    #pragma unroll
    for (int i = 0; i < 4; i++)
        #pragma unroll
        for (int j = 0; j < 4; j++)
            #pragma unroll
            for (int q = 0; q < 4; q++) acc[i][j][q] = 0.f;

    gemm_block<HID>(g_wp + ((size_t)b * 256 + o0) * HID, HID,
                    g_q + ((size_t)b * NPIX + n0) * HID, HID,
                    sbase, acc);
    acc_to_smem(S, acc);

    const int col = tid & 127;
    const int half = tid >> 7;
    const int pixel = n0 + col;
    float lsum = 0.f, lsq = 0.f;

    #pragma unroll 4
    for (int r = half * 64; r < half * 64 + 64; r++) {
        float val = S[r * SROW + col] + bias_s[r];
        lsum += val;
        lsq  += val * val;
        g_o16[((size_t)b * 256 + o0 + r) * NPIX + pixel] = __float2half(val);
    }
    #pragma unroll
    for (int off = 16; off > 0; off >>= 1) {
        lsum += __shfl_down_sync(0xffffffffu, lsum, off);
        lsq  += __shfl_down_sync(0xffffffffu, lsq,  off);
    }
    if ((tid & 31) == 0) {
        atomicAdd(&g_stats[b * 2 + 0], lsum);
        atomicAdd(&g_stats[b * 2 + 1], lsq);
    }
}

// ---------------- kernel: groupnorm normalize (fp16 in, fp32 out) --------
__global__ void __launch_bounds__(256) k_norm(
    const float* __restrict__ gamma, const float* __restrict__ beta,
    float* __restrict__ out)
{
    size_t idx = ((size_t)blockIdx.x * 256 + threadIdx.x) * 4;
    int b = (int)(idx >> 20);
    int c = (int)((idx >> 12) & 255);
    float s1 = g_stats[b * 2 + 0];
    float s2 = g_stats[b * 2 + 1];
    float mu  = s1 * (1.f / NEL_F);
    float var = s2 * (1.f / NEL_F) - mu * mu;
    float rs = rsqrtf(var + GN_EPS);
    float gm = gamma[c] * rs;
    float bb = beta[c] - mu * gm;
    uint2 pk = *(const uint2*)&g_o16[idx];
    __half2 h0 = *(__half2*)&pk.x;
    __half2 h1 = *(__half2*)&pk.y;
    float4 v;
    v.x = __low2float(h0)  * gm + bb;
    v.y = __high2float(h0) * gm + bb;
    v.z = __low2float(h1)  * gm + bb;
    v.w = __high2float(h1) * gm + bb;
    *(float4*)&out[idx] = v;
}

// ---------------- launch ----------------
extern "C" void kernel_launch(void* const* d_in, const int* in_sizes, int n_in,
                              void* d_out, int out_size)
{
    const float* x     = (const float*)d_in[0];
    const float* Wqkv  = (const float*)d_in[1];
    const float* bqkv  = (const float*)d_in[2];
    const float* Wout  = (const float*)d_in[3];
    const float* bout  = (const float*)d_in[4];
    const float* gamma = (const float*)d_in[5];
    const float* beta  = (const float*)d_in[6];
    float* out = (float*)d_out;

    static bool attr_done = false;
    if (!attr_done) {
        cudaFuncSetAttribute(k_qkv_mma,  cudaFuncAttributeMaxDynamicSharedMemorySize, SMEM_BYTES);
        cudaFuncSetAttribute(k_proj_mma, cudaFuncAttributeMaxDynamicSharedMemorySize, SMEM_BYTES);
        attr_done = true;
    }

    k_conv <<<dim3(32, 8, 32), 128>>>(x);
    k_wconv<<<512, 256>>>(Wqkv);
    k_qkv_mma <<<dim3(32, 3, 32), 256, SMEM_BYTES>>>(bqkv);
    k_ctx  <<<dim3(128, 8), 128>>>();
    k_wp   <<<dim3(32, 8), 256>>>(Wout);
    k_proj_mma<<<dim3(32, 2, 32), 256, SMEM_BYTES>>>(bout);
    k_norm <<<32768, 256>>>(gamma, beta, out);
}